// round 5
// baseline (speedup 1.0000x reference)
#include <cuda_runtime.h>
#include <cuda_bf16.h>
#include <math.h>
#include <stdint.h>

#define E_DIM   1024
#define HID_DIM 4096
#define M_TOT   16384          // B*S = 4*4096
#define NWIN    256            // 4*64 windows of 64 tokens
#define SM_SCALE 0.03125f      // 1024^-0.5
#define LN_EPS  1e-5f

// ---- GEMM tiling (mma.sync path; tcgen05 not available at compute_103) ----
#define BM 128
#define BN 256
#define BK 32                  // K elems per stage
#define SROW 40                // padded row length in bf16 elems (80B)
#define APL 10240              // A plane bytes  (128*40*2)
#define BPL 20480              // B plane bytes  (256*40*2)
#define STG 61440              // stage bytes: Ah+Al+Bh+Bl
#define NSTAGE 3
#define SMEM_TOTAL (NSTAGE*STG)   // 184320

// -------- scratch (device globals; no allocation allowed) --------
__device__ float g_q  [M_TOT * E_DIM];
__device__ float g_k  [M_TOT * E_DIM];
__device__ float g_v  [M_TOT * E_DIM];
__device__ float g_att[M_TOT * E_DIM];
__device__ float g_x1 [M_TOT * E_DIM];
__device__ float g_f  [M_TOT * E_DIM];

__device__ __nv_bfloat16 g_xh [M_TOT * E_DIM];
__device__ __nv_bfloat16 g_xl [M_TOT * E_DIM];
__device__ __nv_bfloat16 g_x1h[M_TOT * E_DIM];
__device__ __nv_bfloat16 g_x1l[M_TOT * E_DIM];
__device__ __nv_bfloat16 g_hh [M_TOT * HID_DIM];
__device__ __nv_bfloat16 g_hl [M_TOT * HID_DIM];

__device__ __nv_bfloat16 g_wqh[E_DIM * E_DIM];
__device__ __nv_bfloat16 g_wql[E_DIM * E_DIM];
__device__ __nv_bfloat16 g_wkh[E_DIM * E_DIM];
__device__ __nv_bfloat16 g_wkl[E_DIM * E_DIM];
__device__ __nv_bfloat16 g_wvh[E_DIM * E_DIM];
__device__ __nv_bfloat16 g_wvl[E_DIM * E_DIM];
__device__ __nv_bfloat16 g_w1h[E_DIM * HID_DIM];
__device__ __nv_bfloat16 g_w1l[E_DIM * HID_DIM];
__device__ __nv_bfloat16 g_w2h[HID_DIM * E_DIM];
__device__ __nv_bfloat16 g_w2l[HID_DIM * E_DIM];

// ====================================================================
// helpers
// ====================================================================
__device__ __forceinline__ void split_f32(float x, __nv_bfloat16& hi, __nv_bfloat16& lo) {
    hi = __float2bfloat16(x);
    lo = __float2bfloat16(x - __bfloat162float(hi));
}

__device__ __forceinline__ void mma16816(float* c, const uint32_t* a, const uint32_t* b) {
    asm volatile(
        "mma.sync.aligned.m16n8k16.row.col.f32.bf16.bf16.f32 "
        "{%0,%1,%2,%3},{%4,%5,%6,%7},{%8,%9},{%0,%1,%2,%3};"
        : "+f"(c[0]), "+f"(c[1]), "+f"(c[2]), "+f"(c[3])
        : "r"(a[0]), "r"(a[1]), "r"(a[2]), "r"(a[3]), "r"(b[0]), "r"(b[1]));
}

__device__ __forceinline__ void ldsm4(uint32_t& r0, uint32_t& r1, uint32_t& r2, uint32_t& r3,
                                      uint32_t addr) {
    asm volatile("ldmatrix.sync.aligned.m8n8.x4.shared.b16 {%0,%1,%2,%3},[%4];"
                 : "=r"(r0), "=r"(r1), "=r"(r2), "=r"(r3) : "r"(addr));
}

// ====================================================================
// elementwise split: X fp32 -> hi/lo bf16 planes
// ====================================================================
__global__ __launch_bounds__(256) void split_kernel(
    const float* __restrict__ X, __nv_bfloat16* __restrict__ H,
    __nv_bfloat16* __restrict__ L, int n4)
{
    int i = blockIdx.x * 256 + threadIdx.x;
    if (i >= n4) return;
    float4 v = ((const float4*)X)[i];
    __nv_bfloat16 h[4], l[4];
    split_f32(v.x, h[0], l[0]); split_f32(v.y, h[1], l[1]);
    split_f32(v.z, h[2], l[2]); split_f32(v.w, h[3], l[3]);
    __nv_bfloat162* Hp = (__nv_bfloat162*)(H + (size_t)i * 4);
    __nv_bfloat162* Lp = (__nv_bfloat162*)(L + (size_t)i * 4);
    Hp[0] = __nv_bfloat162{h[0], h[1]}; Hp[1] = __nv_bfloat162{h[2], h[3]};
    Lp[0] = __nv_bfloat162{l[0], l[1]}; Lp[1] = __nv_bfloat162{l[2], l[3]};
}

// ====================================================================
// weight transpose + split: W[K,N] fp32 -> Th[N,K], Tl[N,K] bf16
// ====================================================================
__global__ __launch_bounds__(256) void wtrans_kernel(
    const float* __restrict__ W, __nv_bfloat16* __restrict__ Th,
    __nv_bfloat16* __restrict__ Tl, int K, int N)
{
    __shared__ float t[32][33];
    const int tx = threadIdx.x, ty = threadIdx.y;
    const int n0 = blockIdx.x * 32, k0 = blockIdx.y * 32;
#pragma unroll
    for (int i = ty; i < 32; i += 8)
        t[i][tx] = W[(size_t)(k0 + i) * N + n0 + tx];
    __syncthreads();
#pragma unroll
    for (int i = ty; i < 32; i += 8) {
        float v = t[tx][i];
        __nv_bfloat16 hi, lo; split_f32(v, hi, lo);
        size_t o = (size_t)(n0 + i) * K + k0 + tx;
        Th[o] = hi; Tl[o] = lo;
    }
}

// ====================================================================
// GEMM (TN): C[M,N] = (Ah+Al)[M,K] @ (Bh+Bl)[N,K]^T + bias
//   3-term bf16 split via mma.sync m16n8k16, ldmatrix fragment loads.
//   128x256x32 tiles, 8 warps of 64x64, 3-stage cp.async pipeline.
//   EPI=0: C fp32.  EPI=1: relu, write hi/lo bf16 planes Ch/Cl.
// ====================================================================
template <int EPI>
__global__ __launch_bounds__(256, 1) void gemm_tn(
    const __nv_bfloat16* __restrict__ Ah, const __nv_bfloat16* __restrict__ Al,
    const __nv_bfloat16* __restrict__ Bh, const __nv_bfloat16* __restrict__ Bl,
    const float* __restrict__ bias,
    float* __restrict__ C, __nv_bfloat16* __restrict__ Ch, __nv_bfloat16* __restrict__ Cl,
    int M, int N, int K)
{
    extern __shared__ __align__(16) char smem_raw[];
    const int tid = threadIdx.x;
    const int bm0 = blockIdx.y * BM;
    const int bn0 = blockIdx.x * BN;
    const int lane = tid & 31, w = tid >> 5;
    const int g = lane >> 2, q4 = lane & 3;
    const int wm = (w >> 2) * 64;     // 0 or 64
    const int wn = (w & 3) * 64;      // 0,64,128,192

    const uint32_t sbase = (uint32_t)__cvta_generic_to_shared(smem_raw);

    // ldmatrix per-lane base offsets (bytes within a plane, at k-chunk col 0)
    const uint32_t aoff = (uint32_t)((wm + (lane & 15)) * (SROW * 2) + (lane >> 4) * 16);
    const uint32_t boff = (uint32_t)((wn + (lane >> 4) * 8 + (lane & 7)) * (SROW * 2)
                                     + ((lane >> 3) & 1) * 16);

    float acc[4][8][4];
#pragma unroll
    for (int i = 0; i < 4; i++)
#pragma unroll
        for (int j = 0; j < 8; j++)
#pragma unroll
            for (int r = 0; r < 4; r++) acc[i][j][r] = 0.f;

    auto load_stage = [&](int s, int k0) {
        uint32_t sb = sbase + s * STG;
        // A planes: 128 rows x 32 cols, 512 16B chunks per plane
        {
            const __nv_bfloat16* asrc[2] = {Ah, Al};
#pragma unroll
            for (int p = 0; p < 2; p++) {
#pragma unroll
                for (int t = 0; t < 2; t++) {
                    int c = tid + t * 256;
                    int row = c >> 2, cc = c & 3;
                    uint32_t sa = sb + p * APL + (uint32_t)(row * SROW + cc * 8) * 2;
                    const void* gp = asrc[p] + (size_t)(bm0 + row) * K + k0 + cc * 8;
                    asm volatile("cp.async.cg.shared.global [%0],[%1],16;" :: "r"(sa), "l"(gp));
                }
            }
        }
        // B planes: 256 rows x 32 cols, 1024 chunks per plane
        {
            const __nv_bfloat16* bsrc[2] = {Bh, Bl};
#pragma unroll
            for (int p = 0; p < 2; p++) {
#pragma unroll
                for (int t = 0; t < 4; t++) {
                    int c = tid + t * 256;
                    int row = c >> 2, cc = c & 3;
                    uint32_t sa = sb + 2 * APL + p * BPL + (uint32_t)(row * SROW + cc * 8) * 2;
                    const void* gp = bsrc[p] + (size_t)(bn0 + row) * K + k0 + cc * 8;
                    asm volatile("cp.async.cg.shared.global [%0],[%1],16;" :: "r"(sa), "l"(gp));
                }
            }
        }
        asm volatile("cp.async.commit_group;");
    };

    const int KT = K / BK;
    load_stage(0, 0);
    load_stage(1, BK);

    for (int kt = 0; kt < KT; kt++) {
        const int s = kt % NSTAGE;
        if (kt + 1 < KT) asm volatile("cp.async.wait_group 1;");
        else             asm volatile("cp.async.wait_group 0;");
        __syncthreads();
        if (kt + 2 < KT) load_stage((kt + 2) % NSTAGE, (kt + 2) * BK);

        const uint32_t stg = sbase + s * STG;

#pragma unroll
        for (int ks = 0; ks < 2; ks++) {
            const uint32_t ka = stg + ks * 32 + aoff;                 // A-hi plane
            const uint32_t kb = stg + 2 * APL + ks * 32 + boff;       // B-hi plane

            uint32_t ah[4][4];
#pragma unroll
            for (int tm = 0; tm < 4; tm++)
                ldsm4(ah[tm][0], ah[tm][1], ah[tm][2], ah[tm][3], ka + tm * 16 * (SROW * 2));

            uint32_t bh[8][2];
#pragma unroll
            for (int u = 0; u < 4; u++)
                ldsm4(bh[2 * u][0], bh[2 * u][1], bh[2 * u + 1][0], bh[2 * u + 1][1],
                      kb + u * 16 * (SROW * 2));

#pragma unroll
            for (int tm = 0; tm < 4; tm++)
#pragma unroll
                for (int tn = 0; tn < 8; tn++)
                    mma16816(acc[tm][tn], ah[tm], bh[tn]);

            uint32_t al[4][4];
#pragma unroll
            for (int tm = 0; tm < 4; tm++)
                ldsm4(al[tm][0], al[tm][1], al[tm][2], al[tm][3],
                      ka + APL + tm * 16 * (SROW * 2));

#pragma unroll
            for (int tm = 0; tm < 4; tm++)
#pragma unroll
                for (int tn = 0; tn < 8; tn++)
                    mma16816(acc[tm][tn], al[tm], bh[tn]);

            uint32_t bl[8][2];
#pragma unroll
            for (int u = 0; u < 4; u++)
                ldsm4(bl[2 * u][0], bl[2 * u][1], bl[2 * u + 1][0], bl[2 * u + 1][1],
                      kb + BPL + u * 16 * (SROW * 2));

#pragma unroll
            for (int tm = 0; tm < 4; tm++)
#pragma unroll
                for (int tn = 0; tn < 8; tn++)
                    mma16816(acc[tm][tn], ah[tm], bl[tn]);
        }
    }

    // epilogue
#pragma unroll
    for (int tm = 0; tm < 4; tm++) {
#pragma unroll
        for (int tn = 0; tn < 8; tn++) {
            int r0 = bm0 + wm + tm * 16 + g;
            int col = bn0 + wn + tn * 8 + q4 * 2;
            float b0 = bias[col], b1 = bias[col + 1];
            float v00 = acc[tm][tn][0] + b0, v01 = acc[tm][tn][1] + b1;
            float v10 = acc[tm][tn][2] + b0, v11 = acc[tm][tn][3] + b1;
            if (EPI == 0) {
                *(float2*)(C + (size_t)r0 * N + col) = make_float2(v00, v01);
                *(float2*)(C + (size_t)(r0 + 8) * N + col) = make_float2(v10, v11);
            } else {
                v00 = fmaxf(v00, 0.f); v01 = fmaxf(v01, 0.f);
                v10 = fmaxf(v10, 0.f); v11 = fmaxf(v11, 0.f);
                __nv_bfloat16 h00, l00, h01, l01, h10, l10, h11, l11;
                split_f32(v00, h00, l00); split_f32(v01, h01, l01);
                split_f32(v10, h10, l10); split_f32(v11, h11, l11);
                *(__nv_bfloat162*)(Ch + (size_t)r0 * N + col)       = __nv_bfloat162{h00, h01};
                *(__nv_bfloat162*)(Cl + (size_t)r0 * N + col)       = __nv_bfloat162{l00, l01};
                *(__nv_bfloat162*)(Ch + (size_t)(r0 + 8) * N + col) = __nv_bfloat162{h10, h11};
                *(__nv_bfloat162*)(Cl + (size_t)(r0 + 8) * N + col) = __nv_bfloat162{l10, l11};
            }
        }
    }
}

// ====================================================================
// Window attention: one block per 64-token window
// ====================================================================
__global__ __launch_bounds__(256) void attn_kernel(
    const float* __restrict__ Q, const float* __restrict__ K,
    const float* __restrict__ V, float* __restrict__ O)
{
    __shared__ float sQ [64 * 32];
    __shared__ float sKV[64 * 33];
    __shared__ float sS [64 * 64];

    const int tid  = threadIdx.x;
    const size_t base = (size_t)blockIdx.x * 64 * E_DIM;

    const int kcol = tid & 63;
    const int q0   = (tid >> 6) * 16;
    float acc[16];
#pragma unroll
    for (int i = 0; i < 16; i++) acc[i] = 0.f;

    for (int c0 = 0; c0 < E_DIM; c0 += 32) {
        for (int idx = tid; idx < 64 * 32; idx += 256) {
            int r = idx >> 5, c = idx & 31;
            sQ [r * 32 + c] = Q[base + (size_t)r * E_DIM + c0 + c];
            sKV[r * 33 + c] = K[base + (size_t)r * E_DIM + c0 + c];
        }
        __syncthreads();
#pragma unroll
        for (int c = 0; c < 32; c++) {
            float kv = sKV[kcol * 33 + c];
#pragma unroll
            for (int i = 0; i < 16; i++)
                acc[i] += sQ[(q0 + i) * 32 + c] * kv;
        }
        __syncthreads();
    }
#pragma unroll
    for (int i = 0; i < 16; i++)
        sS[(q0 + i) * 64 + kcol] = acc[i] * SM_SCALE;
    __syncthreads();

    const int lane = tid & 31, wrp = tid >> 5;
    for (int r = wrp * 8; r < wrp * 8 + 8; r++) {
        float v0 = sS[r * 64 + lane];
        float v1 = sS[r * 64 + 32 + lane];
        float m = fmaxf(v0, v1);
#pragma unroll
        for (int o = 16; o > 0; o >>= 1)
            m = fmaxf(m, __shfl_xor_sync(0xffffffffu, m, o));
        float e0 = __expf(v0 - m), e1 = __expf(v1 - m);
        float s = e0 + e1;
#pragma unroll
        for (int o = 16; o > 0; o >>= 1)
            s += __shfl_xor_sync(0xffffffffu, s, o);
        float inv = 1.0f / s;
        sS[r * 64 + lane]      = e0 * inv;
        sS[r * 64 + 32 + lane] = e1 * inv;
    }
    __syncthreads();

    const int ecol = tid & 31;
    const int q0b  = (tid >> 5) * 8;
    for (int c0 = 0; c0 < E_DIM; c0 += 32) {
        for (int idx = tid; idx < 64 * 32; idx += 256) {
            int r = idx >> 5, c = idx & 31;
            sKV[r * 33 + c] = V[base + (size_t)r * E_DIM + c0 + c];
        }
        __syncthreads();
        float oacc[8];
#pragma unroll
        for (int i = 0; i < 8; i++) oacc[i] = 0.f;
#pragma unroll
        for (int k = 0; k < 64; k++) {
            float vv = sKV[k * 33 + ecol];
#pragma unroll
            for (int i = 0; i < 8; i++)
                oacc[i] += sS[(q0b + i) * 64 + k] * vv;
        }
#pragma unroll
        for (int i = 0; i < 8; i++)
            O[base + (size_t)(q0b + i) * E_DIM + c0 + ecol] = oacc[i];
        __syncthreads();
    }
}

// ====================================================================
// Y = LayerNorm(A + R) * g + b.  SPLIT: also emit hi/lo bf16 planes.
// ====================================================================
template <bool SPLIT>
__global__ __launch_bounds__(256) void add_ln_kernel(
    const float* __restrict__ A, const float* __restrict__ R,
    const float* __restrict__ g, const float* __restrict__ b,
    float* __restrict__ Y, __nv_bfloat16* __restrict__ Yh,
    __nv_bfloat16* __restrict__ Yl)
{
    const size_t off = (size_t)blockIdx.x * E_DIM;
    const int tid = threadIdx.x;
    float v[4];
    float s = 0.f, s2 = 0.f;
#pragma unroll
    for (int i = 0; i < 4; i++) {
        int c = tid + i * 256;
        float t = A[off + c] + R[off + c];
        v[i] = t; s += t; s2 += t * t;
    }
#pragma unroll
    for (int o = 16; o > 0; o >>= 1) {
        s  += __shfl_xor_sync(0xffffffffu, s,  o);
        s2 += __shfl_xor_sync(0xffffffffu, s2, o);
    }
    __shared__ float rs[8], rs2[8];
    __shared__ float s_mean, s_rstd;
    const int lane = tid & 31, wrp = tid >> 5;
    if (lane == 0) { rs[wrp] = s; rs2[wrp] = s2; }
    __syncthreads();
    if (tid == 0) {
        float a = 0.f, a2 = 0.f;
#pragma unroll
        for (int i = 0; i < 8; i++) { a += rs[i]; a2 += rs2[i]; }
        float mean = a * (1.0f / E_DIM);
        float var  = a2 * (1.0f / E_DIM) - mean * mean;
        s_mean = mean;
        s_rstd = rsqrtf(var + LN_EPS);
    }
    __syncthreads();
    const float mean = s_mean, rstd = s_rstd;
#pragma unroll
    for (int i = 0; i < 4; i++) {
        int c = tid + i * 256;
        float y = (v[i] - mean) * rstd * g[c] + b[c];
        if (Y) Y[off + c] = y;
        if (SPLIT) {
            __nv_bfloat16 hi, lo; split_f32(y, hi, lo);
            Yh[off + c] = hi; Yl[off + c] = lo;
        }
    }
}

// ====================================================================
extern "C" void kernel_launch(void* const* d_in, const int* in_sizes, int n_in,
                              void* d_out, int out_size)
{
    (void)in_sizes; (void)n_in; (void)out_size;
    const float* x   = (const float*)d_in[0];
    const float* Wq  = (const float*)d_in[1];
    const float* bq  = (const float*)d_in[2];
    const float* Wk  = (const float*)d_in[3];
    const float* bk  = (const float*)d_in[4];
    const float* Wv  = (const float*)d_in[5];
    const float* bv  = (const float*)d_in[6];
    const float* g1  = (const float*)d_in[7];
    const float* be1 = (const float*)d_in[8];
    const float* W1  = (const float*)d_in[9];
    const float* b1  = (const float*)d_in[10];
    const float* W2  = (const float*)d_in[11];
    const float* b2  = (const float*)d_in[12];
    const float* g2  = (const float*)d_in[13];
    const float* be2 = (const float*)d_in[14];
    float* out = (float*)d_out;

    float *q, *k, *v, *att, *x1, *f;
    cudaGetSymbolAddress((void**)&q,   g_q);
    cudaGetSymbolAddress((void**)&k,   g_k);
    cudaGetSymbolAddress((void**)&v,   g_v);
    cudaGetSymbolAddress((void**)&att, g_att);
    cudaGetSymbolAddress((void**)&x1,  g_x1);
    cudaGetSymbolAddress((void**)&f,   g_f);

    __nv_bfloat16 *xh, *xl, *x1h, *x1l, *hh, *hl;
    __nv_bfloat16 *wqh, *wql, *wkh, *wkl, *wvh, *wvl, *w1h, *w1l, *w2h, *w2l;
    cudaGetSymbolAddress((void**)&xh,  g_xh);
    cudaGetSymbolAddress((void**)&xl,  g_xl);
    cudaGetSymbolAddress((void**)&x1h, g_x1h);
    cudaGetSymbolAddress((void**)&x1l, g_x1l);
    cudaGetSymbolAddress((void**)&hh,  g_hh);
    cudaGetSymbolAddress((void**)&hl,  g_hl);
    cudaGetSymbolAddress((void**)&wqh, g_wqh);
    cudaGetSymbolAddress((void**)&wql, g_wql);
    cudaGetSymbolAddress((void**)&wkh, g_wkh);
    cudaGetSymbolAddress((void**)&wkl, g_wkl);
    cudaGetSymbolAddress((void**)&wvh, g_wvh);
    cudaGetSymbolAddress((void**)&wvl, g_wvl);
    cudaGetSymbolAddress((void**)&w1h, g_w1h);
    cudaGetSymbolAddress((void**)&w1l, g_w1l);
    cudaGetSymbolAddress((void**)&w2h, g_w2h);
    cudaGetSymbolAddress((void**)&w2l, g_w2l);

    cudaFuncSetAttribute(gemm_tn<0>, cudaFuncAttributeMaxDynamicSharedMemorySize, SMEM_TOTAL);
    cudaFuncSetAttribute(gemm_tn<1>, cudaFuncAttributeMaxDynamicSharedMemorySize, SMEM_TOTAL);

    dim3 blk(256);
    dim3 tblk(32, 8);

    // operand prep
    split_kernel<<<(M_TOT * E_DIM / 4 + 255) / 256, blk>>>(x, xh, xl, M_TOT * E_DIM / 4);
    wtrans_kernel<<<dim3(E_DIM / 32, E_DIM / 32), tblk>>>(Wq, wqh, wql, E_DIM, E_DIM);
    wtrans_kernel<<<dim3(E_DIM / 32, E_DIM / 32), tblk>>>(Wk, wkh, wkl, E_DIM, E_DIM);
    wtrans_kernel<<<dim3(E_DIM / 32, E_DIM / 32), tblk>>>(Wv, wvh, wvl, E_DIM, E_DIM);
    wtrans_kernel<<<dim3(HID_DIM / 32, E_DIM / 32), tblk>>>(W1, w1h, w1l, E_DIM, HID_DIM);
    wtrans_kernel<<<dim3(E_DIM / 32, HID_DIM / 32), tblk>>>(W2, w2h, w2l, HID_DIM, E_DIM);

    // QKV projections (tensor core)
    dim3 grid_qkv(E_DIM / BN, M_TOT / BM);       // (4, 128)
    gemm_tn<0><<<grid_qkv, blk, SMEM_TOTAL>>>(xh, xl, wqh, wql, bq, q, nullptr, nullptr, M_TOT, E_DIM, E_DIM);
    gemm_tn<0><<<grid_qkv, blk, SMEM_TOTAL>>>(xh, xl, wkh, wkl, bk, k, nullptr, nullptr, M_TOT, E_DIM, E_DIM);
    gemm_tn<0><<<grid_qkv, blk, SMEM_TOTAL>>>(xh, xl, wvh, wvl, bv, v, nullptr, nullptr, M_TOT, E_DIM, E_DIM);

    // per-window attention
    attn_kernel<<<NWIN, blk>>>(q, k, v, att);

    // x1 = LN(x + att), emit fp32 + bf16 planes
    add_ln_kernel<true><<<M_TOT, blk>>>(x, att, g1, be1, x1, x1h, x1l);

    // FFN1: h = relu(x1 @ W1 + b1), write hi/lo planes directly
    dim3 grid_f1(HID_DIM / BN, M_TOT / BM);      // (16, 128)
    gemm_tn<1><<<grid_f1, blk, SMEM_TOTAL>>>(x1h, x1l, w1h, w1l, b1, nullptr, hh, hl, M_TOT, HID_DIM, E_DIM);

    // FFN2: f = h @ W2 + b2 (fp32)
    dim3 grid_f2(E_DIM / BN, M_TOT / BM);        // (4, 128)
    gemm_tn<0><<<grid_f2, blk, SMEM_TOTAL>>>(hh, hl, w2h, w2l, b2, f, nullptr, nullptr, M_TOT, E_DIM, HID_DIM);

    // out = LN(x1 + f)
    add_ln_kernel<false><<<M_TOT, blk>>>(x1, f, g2, be2, out, nullptr, nullptr);
}

// round 6
// speedup vs baseline: 1.4869x; 1.4869x over previous
#include <cuda_runtime.h>
#include <cuda_fp16.h>
#include <math.h>
#include <stdint.h>

#define E_DIM   1024
#define HID_DIM 4096
#define M_TOT   16384          // B*S = 4*4096
#define NWIN    256            // 4*64 windows of 64 tokens
#define SM_SCALE 0.03125f      // 1024^-0.5
#define LN_EPS  1e-5f

// ---- GEMM tiling (mma.sync fp16 path) ----
#define BM 128
#define BN 128
#define BK 32                  // K elems per stage
#define SROW 40                // padded row length in fp16 elems (80B)
#define PL 10240               // plane bytes (128*40*2)
#define STG 30720              // stage bytes: Ah+Al+B
#define NSTAGE 3
#define SMEM_TOTAL (NSTAGE*STG)   // 92160

// -------- scratch (device globals; no allocation allowed) --------
__device__ float g_q  [M_TOT * E_DIM];
__device__ float g_k  [M_TOT * E_DIM];
__device__ float g_v  [M_TOT * E_DIM];
__device__ float g_att[M_TOT * E_DIM];
__device__ float g_x1 [M_TOT * E_DIM];
__device__ float g_f  [M_TOT * E_DIM];

__device__ __half g_xh [M_TOT * E_DIM];
__device__ __half g_xl [M_TOT * E_DIM];
__device__ __half g_x1h[M_TOT * E_DIM];
__device__ __half g_x1l[M_TOT * E_DIM];
__device__ __half g_hh [M_TOT * HID_DIM];
__device__ __half g_hl [M_TOT * HID_DIM];

__device__ __half g_wq [E_DIM * E_DIM];
__device__ __half g_wk [E_DIM * E_DIM];
__device__ __half g_wv [E_DIM * E_DIM];
__device__ __half g_w1 [E_DIM * HID_DIM];
__device__ __half g_w2 [HID_DIM * E_DIM];

// ====================================================================
// helpers
// ====================================================================
__device__ __forceinline__ void split_f32h(float x, __half& hi, __half& lo) {
    hi = __float2half(x);
    lo = __float2half(x - __half2float(hi));
}

__device__ __forceinline__ void mma16816(float* c, const uint32_t* a, const uint32_t* b) {
    asm volatile(
        "mma.sync.aligned.m16n8k16.row.col.f32.f16.f16.f32 "
        "{%0,%1,%2,%3},{%4,%5,%6,%7},{%8,%9},{%0,%1,%2,%3};"
        : "+f"(c[0]), "+f"(c[1]), "+f"(c[2]), "+f"(c[3])
        : "r"(a[0]), "r"(a[1]), "r"(a[2]), "r"(a[3]), "r"(b[0]), "r"(b[1]));
}

__device__ __forceinline__ void ldsm4(uint32_t& r0, uint32_t& r1, uint32_t& r2, uint32_t& r3,
                                      uint32_t addr) {
    asm volatile("ldmatrix.sync.aligned.m8n8.x4.shared.b16 {%0,%1,%2,%3},[%4];"
                 : "=r"(r0), "=r"(r1), "=r"(r2), "=r"(r3) : "r"(addr));
}

// ====================================================================
// elementwise split: X fp32 -> hi/lo fp16 planes
// ====================================================================
__global__ __launch_bounds__(256) void split_kernel(
    const float* __restrict__ X, __half* __restrict__ H,
    __half* __restrict__ L, int n4)
{
    int i = blockIdx.x * 256 + threadIdx.x;
    if (i >= n4) return;
    float4 v = ((const float4*)X)[i];
    __half h[4], l[4];
    split_f32h(v.x, h[0], l[0]); split_f32h(v.y, h[1], l[1]);
    split_f32h(v.z, h[2], l[2]); split_f32h(v.w, h[3], l[3]);
    __half2* Hp = (__half2*)(H + (size_t)i * 4);
    __half2* Lp = (__half2*)(L + (size_t)i * 4);
    Hp[0] = __half2{h[0], h[1]}; Hp[1] = __half2{h[2], h[3]};
    Lp[0] = __half2{l[0], l[1]}; Lp[1] = __half2{l[2], l[3]};
}

// ====================================================================
// weight transpose: W[K,N] fp32 -> T[N,K] fp16
// ====================================================================
__global__ __launch_bounds__(256) void wtrans_kernel(
    const float* __restrict__ W, __half* __restrict__ T, int K, int N)
{
    __shared__ float t[32][33];
    const int tx = threadIdx.x, ty = threadIdx.y;
    const int n0 = blockIdx.x * 32, k0 = blockIdx.y * 32;
#pragma unroll
    for (int i = ty; i < 32; i += 8)
        t[i][tx] = W[(size_t)(k0 + i) * N + n0 + tx];
    __syncthreads();
#pragma unroll
    for (int i = ty; i < 32; i += 8)
        T[(size_t)(n0 + i) * K + k0 + tx] = __float2half(t[tx][i]);
}

// ====================================================================
// GEMM (TN): C[M,N] = (Ah+Al)[M,K] @ B[N,K]^T + bias
//   2-term fp16 split via mma.sync m16n8k16, ldmatrix fragment loads.
//   128x128x32 tiles, 8 warps of 64x32, 3-stage cp.async pipeline.
//   EPI=0: C fp32.  EPI=1: relu, write hi/lo fp16 planes Ch/Cl.
// ====================================================================
template <int EPI>
__global__ __launch_bounds__(256, 2) void gemm_tn(
    const __half* __restrict__ Ah, const __half* __restrict__ Al,
    const __half* __restrict__ B,
    const float* __restrict__ bias,
    float* __restrict__ C, __half* __restrict__ Ch, __half* __restrict__ Cl,
    int M, int N, int K)
{
    extern __shared__ __align__(16) char smem_raw[];
    const int tid = threadIdx.x;
    const int bm0 = blockIdx.y * BM;
    const int bn0 = blockIdx.x * BN;
    const int lane = tid & 31, w = tid >> 5;
    const int g = lane >> 2, q4 = lane & 3;
    const int wm = (w >> 2) * 64;     // 0 or 64
    const int wn = (w & 3) * 32;      // 0,32,64,96

    const uint32_t sbase = (uint32_t)__cvta_generic_to_shared(smem_raw);

    // ldmatrix per-lane base offsets (bytes within a plane, at k-chunk col 0)
    const uint32_t aoff = (uint32_t)((wm + (lane & 15)) * (SROW * 2) + (lane >> 4) * 16);
    const uint32_t boff = (uint32_t)((wn + (lane >> 4) * 8 + (lane & 7)) * (SROW * 2)
                                     + ((lane >> 3) & 1) * 16);

    float acc[4][4][4];
#pragma unroll
    for (int i = 0; i < 4; i++)
#pragma unroll
        for (int j = 0; j < 4; j++)
#pragma unroll
            for (int r = 0; r < 4; r++) acc[i][j][r] = 0.f;

    const __half* gp[3] = {Ah, Al, B};
    const int rb[3] = {bm0, bm0, bn0};

    auto load_stage = [&](int s, int k0) {
        uint32_t sb = sbase + s * STG;
#pragma unroll
        for (int p = 0; p < 3; p++) {
#pragma unroll
            for (int t = 0; t < 2; t++) {
                int c = tid + t * 256;
                int row = c >> 2, cc = c & 3;
                uint32_t sa = sb + p * PL + (uint32_t)(row * SROW + cc * 8) * 2;
                const void* gptr = gp[p] + (size_t)(rb[p] + row) * K + k0 + cc * 8;
                asm volatile("cp.async.cg.shared.global [%0],[%1],16;" :: "r"(sa), "l"(gptr));
            }
        }
        asm volatile("cp.async.commit_group;");
    };

    const int KT = K / BK;
    load_stage(0, 0);
    load_stage(1, BK);

    for (int kt = 0; kt < KT; kt++) {
        const int s = kt % NSTAGE;
        if (kt + 1 < KT) asm volatile("cp.async.wait_group 1;");
        else             asm volatile("cp.async.wait_group 0;");
        __syncthreads();
        if (kt + 2 < KT) load_stage((kt + 2) % NSTAGE, (kt + 2) * BK);

        const uint32_t stg = sbase + s * STG;

#pragma unroll
        for (int ks = 0; ks < 2; ks++) {
            const uint32_t ka = stg + ks * 32 + aoff;            // A-hi plane
            const uint32_t kb = stg + 2 * PL + ks * 32 + boff;   // B plane

            uint32_t bfr[4][2];
            ldsm4(bfr[0][0], bfr[0][1], bfr[1][0], bfr[1][1], kb);
            ldsm4(bfr[2][0], bfr[2][1], bfr[3][0], bfr[3][1], kb + 16 * (SROW * 2));

            uint32_t ah[4][4];
#pragma unroll
            for (int tm = 0; tm < 4; tm++)
                ldsm4(ah[tm][0], ah[tm][1], ah[tm][2], ah[tm][3], ka + tm * 16 * (SROW * 2));

#pragma unroll
            for (int tm = 0; tm < 4; tm++)
#pragma unroll
                for (int tn = 0; tn < 4; tn++)
                    mma16816(acc[tm][tn], ah[tm], bfr[tn]);

            uint32_t al[4][4];
#pragma unroll
            for (int tm = 0; tm < 4; tm++)
                ldsm4(al[tm][0], al[tm][1], al[tm][2], al[tm][3],
                      ka + PL + tm * 16 * (SROW * 2));

#pragma unroll
            for (int tm = 0; tm < 4; tm++)
#pragma unroll
                for (int tn = 0; tn < 4; tn++)
                    mma16816(acc[tm][tn], al[tm], bfr[tn]);
        }
    }

    // epilogue
#pragma unroll
    for (int tm = 0; tm < 4; tm++) {
#pragma unroll
        for (int tn = 0; tn < 4; tn++) {
            int r0 = bm0 + wm + tm * 16 + g;
            int col = bn0 + wn + tn * 8 + q4 * 2;
            float b0 = bias[col], b1 = bias[col + 1];
            float v00 = acc[tm][tn][0] + b0, v01 = acc[tm][tn][1] + b1;
            float v10 = acc[tm][tn][2] + b0, v11 = acc[tm][tn][3] + b1;
            if (EPI == 0) {
                *(float2*)(C + (size_t)r0 * N + col) = make_float2(v00, v01);
                *(float2*)(C + (size_t)(r0 + 8) * N + col) = make_float2(v10, v11);
            } else {
                v00 = fmaxf(v00, 0.f); v01 = fmaxf(v01, 0.f);
                v10 = fmaxf(v10, 0.f); v11 = fmaxf(v11, 0.f);
                __half h00, l00, h01, l01, h10, l10, h11, l11;
                split_f32h(v00, h00, l00); split_f32h(v01, h01, l01);
                split_f32h(v10, h10, l10); split_f32h(v11, h11, l11);
                *(__half2*)(Ch + (size_t)r0 * N + col)       = __half2{h00, h01};
                *(__half2*)(Cl + (size_t)r0 * N + col)       = __half2{l00, l01};
                *(__half2*)(Ch + (size_t)(r0 + 8) * N + col) = __half2{h10, h11};
                *(__half2*)(Cl + (size_t)(r0 + 8) * N + col) = __half2{l10, l11};
            }
        }
    }
}

// ====================================================================
// Window attention: one block per 64-token window
// ====================================================================
__global__ __launch_bounds__(256) void attn_kernel(
    const float* __restrict__ Q, const float* __restrict__ K,
    const float* __restrict__ V, float* __restrict__ O)
{
    __shared__ float sQ [64 * 32];
    __shared__ float sKV[64 * 33];
    __shared__ float sS [64 * 64];

    const int tid  = threadIdx.x;
    const size_t base = (size_t)blockIdx.x * 64 * E_DIM;

    const int kcol = tid & 63;
    const int q0   = (tid >> 6) * 16;
    float acc[16];
#pragma unroll
    for (int i = 0; i < 16; i++) acc[i] = 0.f;

    for (int c0 = 0; c0 < E_DIM; c0 += 32) {
        for (int idx = tid; idx < 64 * 32; idx += 256) {
            int r = idx >> 5, c = idx & 31;
            sQ [r * 32 + c] = Q[base + (size_t)r * E_DIM + c0 + c];
            sKV[r * 33 + c] = K[base + (size_t)r * E_DIM + c0 + c];
        }
        __syncthreads();
#pragma unroll
        for (int c = 0; c < 32; c++) {
            float kv = sKV[kcol * 33 + c];
#pragma unroll
            for (int i = 0; i < 16; i++)
                acc[i] += sQ[(q0 + i) * 32 + c] * kv;
        }
        __syncthreads();
    }
#pragma unroll
    for (int i = 0; i < 16; i++)
        sS[(q0 + i) * 64 + kcol] = acc[i] * SM_SCALE;
    __syncthreads();

    const int lane = tid & 31, wrp = tid >> 5;
    for (int r = wrp * 8; r < wrp * 8 + 8; r++) {
        float v0 = sS[r * 64 + lane];
        float v1 = sS[r * 64 + 32 + lane];
        float m = fmaxf(v0, v1);
#pragma unroll
        for (int o = 16; o > 0; o >>= 1)
            m = fmaxf(m, __shfl_xor_sync(0xffffffffu, m, o));
        float e0 = __expf(v0 - m), e1 = __expf(v1 - m);
        float s = e0 + e1;
#pragma unroll
        for (int o = 16; o > 0; o >>= 1)
            s += __shfl_xor_sync(0xffffffffu, s, o);
        float inv = 1.0f / s;
        sS[r * 64 + lane]      = e0 * inv;
        sS[r * 64 + 32 + lane] = e1 * inv;
    }
    __syncthreads();

    const int ecol = tid & 31;
    const int q0b  = (tid >> 5) * 8;
    for (int c0 = 0; c0 < E_DIM; c0 += 32) {
        for (int idx = tid; idx < 64 * 32; idx += 256) {
            int r = idx >> 5, c = idx & 31;
            sKV[r * 33 + c] = V[base + (size_t)r * E_DIM + c0 + c];
        }
        __syncthreads();
        float oacc[8];
#pragma unroll
        for (int i = 0; i < 8; i++) oacc[i] = 0.f;
#pragma unroll
        for (int k = 0; k < 64; k++) {
            float vv = sKV[k * 33 + ecol];
#pragma unroll
            for (int i = 0; i < 8; i++)
                oacc[i] += sS[(q0b + i) * 64 + k] * vv;
        }
#pragma unroll
        for (int i = 0; i < 8; i++)
            O[base + (size_t)(q0b + i) * E_DIM + c0 + ecol] = oacc[i];
        __syncthreads();
    }
}

// ====================================================================
// Y = LayerNorm(A + R) * g + b.  SPLIT: also emit hi/lo fp16 planes.
// ====================================================================
template <bool SPLIT>
__global__ __launch_bounds__(256) void add_ln_kernel(
    const float* __restrict__ A, const float* __restrict__ R,
    const float* __restrict__ g, const float* __restrict__ b,
    float* __restrict__ Y, __half* __restrict__ Yh, __half* __restrict__ Yl)
{
    const size_t off = (size_t)blockIdx.x * E_DIM;
    const int tid = threadIdx.x;
    float v[4];
    float s = 0.f, s2 = 0.f;
#pragma unroll
    for (int i = 0; i < 4; i++) {
        int c = tid + i * 256;
        float t = A[off + c] + R[off + c];
        v[i] = t; s += t; s2 += t * t;
    }
#pragma unroll
    for (int o = 16; o > 0; o >>= 1) {
        s  += __shfl_xor_sync(0xffffffffu, s,  o);
        s2 += __shfl_xor_sync(0xffffffffu, s2, o);
    }
    __shared__ float rs[8], rs2[8];
    __shared__ float s_mean, s_rstd;
    const int lane = tid & 31, wrp = tid >> 5;
    if (lane == 0) { rs[wrp] = s; rs2[wrp] = s2; }
    __syncthreads();
    if (tid == 0) {
        float a = 0.f, a2 = 0.f;
#pragma unroll
        for (int i = 0; i < 8; i++) { a += rs[i]; a2 += rs2[i]; }
        float mean = a * (1.0f / E_DIM);
        float var  = a2 * (1.0f / E_DIM) - mean * mean;
        s_mean = mean;
        s_rstd = rsqrtf(var + LN_EPS);
    }
    __syncthreads();
    const float mean = s_mean, rstd = s_rstd;
#pragma unroll
    for (int i = 0; i < 4; i++) {
        int c = tid + i * 256;
        float y = (v[i] - mean) * rstd * g[c] + b[c];
        if (Y) Y[off + c] = y;
        if (SPLIT) {
            __half hi, lo; split_f32h(y, hi, lo);
            Yh[off + c] = hi; Yl[off + c] = lo;
        }
    }
}

// ====================================================================
extern "C" void kernel_launch(void* const* d_in, const int* in_sizes, int n_in,
                              void* d_out, int out_size)
{
    (void)in_sizes; (void)n_in; (void)out_size;
    const float* x   = (const float*)d_in[0];
    const float* Wq  = (const float*)d_in[1];
    const float* bq  = (const float*)d_in[2];
    const float* Wk  = (const float*)d_in[3];
    const float* bk  = (const float*)d_in[4];
    const float* Wv  = (const float*)d_in[5];
    const float* bv  = (const float*)d_in[6];
    const float* g1  = (const float*)d_in[7];
    const float* be1 = (const float*)d_in[8];
    const float* W1  = (const float*)d_in[9];
    const float* b1  = (const float*)d_in[10];
    const float* W2  = (const float*)d_in[11];
    const float* b2  = (const float*)d_in[12];
    const float* g2  = (const float*)d_in[13];
    const float* be2 = (const float*)d_in[14];
    float* out = (float*)d_out;

    float *q, *k, *v, *att, *x1, *f;
    cudaGetSymbolAddress((void**)&q,   g_q);
    cudaGetSymbolAddress((void**)&k,   g_k);
    cudaGetSymbolAddress((void**)&v,   g_v);
    cudaGetSymbolAddress((void**)&att, g_att);
    cudaGetSymbolAddress((void**)&x1,  g_x1);
    cudaGetSymbolAddress((void**)&f,   g_f);

    __half *xh, *xl, *x1h, *x1l, *hh, *hl, *wq, *wk, *wv, *w1, *w2;
    cudaGetSymbolAddress((void**)&xh,  g_xh);
    cudaGetSymbolAddress((void**)&xl,  g_xl);
    cudaGetSymbolAddress((void**)&x1h, g_x1h);
    cudaGetSymbolAddress((void**)&x1l, g_x1l);
    cudaGetSymbolAddress((void**)&hh,  g_hh);
    cudaGetSymbolAddress((void**)&hl,  g_hl);
    cudaGetSymbolAddress((void**)&wq,  g_wq);
    cudaGetSymbolAddress((void**)&wk,  g_wk);
    cudaGetSymbolAddress((void**)&wv,  g_wv);
    cudaGetSymbolAddress((void**)&w1,  g_w1);
    cudaGetSymbolAddress((void**)&w2,  g_w2);

    cudaFuncSetAttribute(gemm_tn<0>, cudaFuncAttributeMaxDynamicSharedMemorySize, SMEM_TOTAL);
    cudaFuncSetAttribute(gemm_tn<1>, cudaFuncAttributeMaxDynamicSharedMemorySize, SMEM_TOTAL);

    dim3 blk(256);
    dim3 tblk(32, 8);

    // operand prep
    split_kernel<<<(M_TOT * E_DIM / 4 + 255) / 256, blk>>>(x, xh, xl, M_TOT * E_DIM / 4);
    wtrans_kernel<<<dim3(E_DIM / 32, E_DIM / 32), tblk>>>(Wq, wq, E_DIM, E_DIM);
    wtrans_kernel<<<dim3(E_DIM / 32, E_DIM / 32), tblk>>>(Wk, wk, E_DIM, E_DIM);
    wtrans_kernel<<<dim3(E_DIM / 32, E_DIM / 32), tblk>>>(Wv, wv, E_DIM, E_DIM);
    wtrans_kernel<<<dim3(HID_DIM / 32, E_DIM / 32), tblk>>>(W1, w1, E_DIM, HID_DIM);
    wtrans_kernel<<<dim3(E_DIM / 32, HID_DIM / 32), tblk>>>(W2, w2, HID_DIM, E_DIM);

    // QKV projections (tensor core)
    dim3 grid_qkv(E_DIM / BN, M_TOT / BM);       // (8, 128)
    gemm_tn<0><<<grid_qkv, blk, SMEM_TOTAL>>>(xh, xl, wq, bq, q, nullptr, nullptr, M_TOT, E_DIM, E_DIM);
    gemm_tn<0><<<grid_qkv, blk, SMEM_TOTAL>>>(xh, xl, wk, bk, k, nullptr, nullptr, M_TOT, E_DIM, E_DIM);
    gemm_tn<0><<<grid_qkv, blk, SMEM_TOTAL>>>(xh, xl, wv, bv, v, nullptr, nullptr, M_TOT, E_DIM, E_DIM);

    // per-window attention
    attn_kernel<<<NWIN, blk>>>(q, k, v, att);

    // x1 = LN(x + att), emit fp32 + fp16 planes
    add_ln_kernel<true><<<M_TOT, blk>>>(x, att, g1, be1, x1, x1h, x1l);

    // FFN1: h = relu(x1 @ W1 + b1), write hi/lo planes directly
    dim3 grid_f1(HID_DIM / BN, M_TOT / BM);      // (32, 128)
    gemm_tn<1><<<grid_f1, blk, SMEM_TOTAL>>>(x1h, x1l, w1, b1, nullptr, hh, hl, M_TOT, HID_DIM, E_DIM);

    // FFN2: f = h @ W2 + b2 (fp32)
    dim3 grid_f2(E_DIM / BN, M_TOT / BM);        // (8, 128)
    gemm_tn<0><<<grid_f2, blk, SMEM_TOTAL>>>(hh, hl, w2, b2, f, nullptr, nullptr, M_TOT, E_DIM, HID_DIM);

    // out = LN(x1 + f)
    add_ln_kernel<false><<<M_TOT, blk>>>(x1, f, g2, be2, out, nullptr, nullptr);
}

// round 7
// speedup vs baseline: 2.3456x; 1.5775x over previous
#include <cuda_runtime.h>
#include <cuda_fp16.h>
#include <math.h>
#include <stdint.h>

#define E_DIM   1024
#define HID_DIM 4096
#define M_TOT   16384          // B*S = 4*4096
#define NWIN    256            // 4*64 windows of 64 tokens
#define SM_SCALE 0.03125f      // 1024^-0.5
#define LN_EPS  1e-5f

// ---- GEMM tiling (mma.sync fp16, single term) ----
#define BM 128
#define BN 128
#define BK 32                  // K elems per stage
#define SROW 40                // padded row length in fp16 elems (80B)
#define PL 10240               // plane bytes (128*40*2)
#define STG 20480              // stage bytes: A + B
#define NSTAGE 4
#define SMEM_TOTAL (NSTAGE*STG)   // 81920

// -------- scratch (device globals; no allocation allowed) --------
__device__ float g_q  [M_TOT * E_DIM];
__device__ float g_k  [M_TOT * E_DIM];
__device__ float g_v  [M_TOT * E_DIM];
__device__ float g_att[M_TOT * E_DIM];
__device__ float g_x1 [M_TOT * E_DIM];
__device__ float g_f  [M_TOT * E_DIM];

__device__ __half g_xh [M_TOT * E_DIM];
__device__ __half g_x1h[M_TOT * E_DIM];
__device__ __half g_hh [M_TOT * HID_DIM];

__device__ __half g_wq [E_DIM * E_DIM];
__device__ __half g_wk [E_DIM * E_DIM];
__device__ __half g_wv [E_DIM * E_DIM];
__device__ __half g_w1 [E_DIM * HID_DIM];
__device__ __half g_w2 [HID_DIM * E_DIM];

// ====================================================================
// helpers
// ====================================================================
__device__ __forceinline__ void mma16816(float* c, const uint32_t* a, const uint32_t* b) {
    asm volatile(
        "mma.sync.aligned.m16n8k16.row.col.f32.f16.f16.f32 "
        "{%0,%1,%2,%3},{%4,%5,%6,%7},{%8,%9},{%0,%1,%2,%3};"
        : "+f"(c[0]), "+f"(c[1]), "+f"(c[2]), "+f"(c[3])
        : "r"(a[0]), "r"(a[1]), "r"(a[2]), "r"(a[3]), "r"(b[0]), "r"(b[1]));
}

__device__ __forceinline__ void ldsm4(uint32_t& r0, uint32_t& r1, uint32_t& r2, uint32_t& r3,
                                      uint32_t addr) {
    asm volatile("ldmatrix.sync.aligned.m8n8.x4.shared.b16 {%0,%1,%2,%3},[%4];"
                 : "=r"(r0), "=r"(r1), "=r"(r2), "=r"(r3) : "r"(addr));
}

// ====================================================================
// elementwise convert: X fp32 -> fp16
// ====================================================================
__global__ __launch_bounds__(256) void cvt_kernel(
    const float* __restrict__ X, __half* __restrict__ H, int n4)
{
    int i = blockIdx.x * 256 + threadIdx.x;
    if (i >= n4) return;
    float4 v = ((const float4*)X)[i];
    __half2* Hp = (__half2*)(H + (size_t)i * 4);
    Hp[0] = __floats2half2_rn(v.x, v.y);
    Hp[1] = __floats2half2_rn(v.z, v.w);
}

// ====================================================================
// weight transpose: W[K,N] fp32 -> T[N,K] fp16
// ====================================================================
__global__ __launch_bounds__(256) void wtrans_kernel(
    const float* __restrict__ W, __half* __restrict__ T, int K, int N)
{
    __shared__ float t[32][33];
    const int tx = threadIdx.x, ty = threadIdx.y;
    const int n0 = blockIdx.x * 32, k0 = blockIdx.y * 32;
#pragma unroll
    for (int i = ty; i < 32; i += 8)
        t[i][tx] = W[(size_t)(k0 + i) * N + n0 + tx];
    __syncthreads();
#pragma unroll
    for (int i = ty; i < 32; i += 8)
        T[(size_t)(n0 + i) * K + k0 + tx] = __float2half(t[tx][i]);
}

// ====================================================================
// GEMM (TN): C[M,N] = A[M,K] @ B[N,K]^T + bias   (fp16 x fp16 -> fp32)
//   128x128x32 tiles, 8 warps of 64x32, 4-stage cp.async pipeline.
//   EPI=0: C fp32.  EPI=1: relu, write fp16 Ch.
// ====================================================================
template <int EPI>
__global__ __launch_bounds__(256, 2) void gemm_tn(
    const __half* __restrict__ A, const __half* __restrict__ B,
    const float* __restrict__ bias,
    float* __restrict__ C, __half* __restrict__ Ch,
    int M, int N, int K)
{
    extern __shared__ __align__(16) char smem_raw[];
    const int tid = threadIdx.x;
    const int bm0 = blockIdx.y * BM;
    const int bn0 = blockIdx.x * BN;
    const int lane = tid & 31, w = tid >> 5;
    const int g = lane >> 2, q4 = lane & 3;
    const int wm = (w >> 2) * 64;     // 0 or 64
    const int wn = (w & 3) * 32;      // 0,32,64,96

    const uint32_t sbase = (uint32_t)__cvta_generic_to_shared(smem_raw);

    const uint32_t aoff = (uint32_t)((wm + (lane & 15)) * (SROW * 2) + (lane >> 4) * 16);
    const uint32_t boff = (uint32_t)((wn + (lane >> 4) * 8 + (lane & 7)) * (SROW * 2)
                                     + ((lane >> 3) & 1) * 16);

    float acc[4][4][4];
#pragma unroll
    for (int i = 0; i < 4; i++)
#pragma unroll
        for (int j = 0; j < 4; j++)
#pragma unroll
            for (int r = 0; r < 4; r++) acc[i][j][r] = 0.f;

    const __half* gp[2] = {A, B};
    const int rb[2] = {bm0, bn0};

    auto load_stage = [&](int s, int k0) {
        uint32_t sb = sbase + s * STG;
#pragma unroll
        for (int p = 0; p < 2; p++) {
#pragma unroll
            for (int t = 0; t < 2; t++) {
                int c = tid + t * 256;
                int row = c >> 2, cc = c & 3;
                uint32_t sa = sb + p * PL + (uint32_t)(row * SROW + cc * 8) * 2;
                const void* gptr = gp[p] + (size_t)(rb[p] + row) * K + k0 + cc * 8;
                asm volatile("cp.async.cg.shared.global [%0],[%1],16;" :: "r"(sa), "l"(gptr));
            }
        }
        asm volatile("cp.async.commit_group;");
    };

    const int KT = K / BK;
    load_stage(0, 0);
    load_stage(1, BK);
    load_stage(2, 2 * BK);

    for (int kt = 0; kt < KT; kt++) {
        const int s = kt % NSTAGE;
        if (kt < KT - 2)      asm volatile("cp.async.wait_group 2;");
        else if (kt == KT - 2) asm volatile("cp.async.wait_group 1;");
        else                  asm volatile("cp.async.wait_group 0;");
        __syncthreads();
        if (kt + 3 < KT) load_stage((kt + 3) % NSTAGE, (kt + 3) * BK);

        const uint32_t stg = sbase + s * STG;

#pragma unroll
        for (int ks = 0; ks < 2; ks++) {
            const uint32_t ka = stg + ks * 32 + aoff;
            const uint32_t kb = stg + PL + ks * 32 + boff;

            uint32_t bfr[4][2];
            ldsm4(bfr[0][0], bfr[0][1], bfr[1][0], bfr[1][1], kb);
            ldsm4(bfr[2][0], bfr[2][1], bfr[3][0], bfr[3][1], kb + 16 * (SROW * 2));

            uint32_t afr[4][4];
#pragma unroll
            for (int tm = 0; tm < 4; tm++)
                ldsm4(afr[tm][0], afr[tm][1], afr[tm][2], afr[tm][3], ka + tm * 16 * (SROW * 2));

#pragma unroll
            for (int tm = 0; tm < 4; tm++)
#pragma unroll
                for (int tn = 0; tn < 4; tn++)
                    mma16816(acc[tm][tn], afr[tm], bfr[tn]);
        }
    }

    // epilogue
#pragma unroll
    for (int tm = 0; tm < 4; tm++) {
#pragma unroll
        for (int tn = 0; tn < 4; tn++) {
            int r0 = bm0 + wm + tm * 16 + g;
            int col = bn0 + wn + tn * 8 + q4 * 2;
            float b0 = bias[col], b1 = bias[col + 1];
            float v00 = acc[tm][tn][0] + b0, v01 = acc[tm][tn][1] + b1;
            float v10 = acc[tm][tn][2] + b0, v11 = acc[tm][tn][3] + b1;
            if (EPI == 0) {
                *(float2*)(C + (size_t)r0 * N + col) = make_float2(v00, v01);
                *(float2*)(C + (size_t)(r0 + 8) * N + col) = make_float2(v10, v11);
            } else {
                v00 = fmaxf(v00, 0.f); v01 = fmaxf(v01, 0.f);
                v10 = fmaxf(v10, 0.f); v11 = fmaxf(v11, 0.f);
                *(__half2*)(Ch + (size_t)r0 * N + col)       = __floats2half2_rn(v00, v01);
                *(__half2*)(Ch + (size_t)(r0 + 8) * N + col) = __floats2half2_rn(v10, v11);
            }
        }
    }
}

// ====================================================================
// Window attention: one block per 64-token window
// ====================================================================
__global__ __launch_bounds__(256) void attn_kernel(
    const float* __restrict__ Q, const float* __restrict__ K,
    const float* __restrict__ V, float* __restrict__ O)
{
    __shared__ float sQ [64 * 32];
    __shared__ float sKV[64 * 33];
    __shared__ float sS [64 * 64];

    const int tid  = threadIdx.x;
    const size_t base = (size_t)blockIdx.x * 64 * E_DIM;

    const int kcol = tid & 63;
    const int q0   = (tid >> 6) * 16;
    float acc[16];
#pragma unroll
    for (int i = 0; i < 16; i++) acc[i] = 0.f;

    for (int c0 = 0; c0 < E_DIM; c0 += 32) {
        for (int idx = tid; idx < 64 * 32; idx += 256) {
            int r = idx >> 5, c = idx & 31;
            sQ [r * 32 + c] = Q[base + (size_t)r * E_DIM + c0 + c];
            sKV[r * 33 + c] = K[base + (size_t)r * E_DIM + c0 + c];
        }
        __syncthreads();
#pragma unroll
        for (int c = 0; c < 32; c++) {
            float kv = sKV[kcol * 33 + c];
#pragma unroll
            for (int i = 0; i < 16; i++)
                acc[i] += sQ[(q0 + i) * 32 + c] * kv;
        }
        __syncthreads();
    }
#pragma unroll
    for (int i = 0; i < 16; i++)
        sS[(q0 + i) * 64 + kcol] = acc[i] * SM_SCALE;
    __syncthreads();

    const int lane = tid & 31, wrp = tid >> 5;
    for (int r = wrp * 8; r < wrp * 8 + 8; r++) {
        float v0 = sS[r * 64 + lane];
        float v1 = sS[r * 64 + 32 + lane];
        float m = fmaxf(v0, v1);
#pragma unroll
        for (int o = 16; o > 0; o >>= 1)
            m = fmaxf(m, __shfl_xor_sync(0xffffffffu, m, o));
        float e0 = __expf(v0 - m), e1 = __expf(v1 - m);
        float s = e0 + e1;
#pragma unroll
        for (int o = 16; o > 0; o >>= 1)
            s += __shfl_xor_sync(0xffffffffu, s, o);
        float inv = 1.0f / s;
        sS[r * 64 + lane]      = e0 * inv;
        sS[r * 64 + 32 + lane] = e1 * inv;
    }
    __syncthreads();

    const int ecol = tid & 31;
    const int q0b  = (tid >> 5) * 8;
    for (int c0 = 0; c0 < E_DIM; c0 += 32) {
        for (int idx = tid; idx < 64 * 32; idx += 256) {
            int r = idx >> 5, c = idx & 31;
            sKV[r * 33 + c] = V[base + (size_t)r * E_DIM + c0 + c];
        }
        __syncthreads();
        float oacc[8];
#pragma unroll
        for (int i = 0; i < 8; i++) oacc[i] = 0.f;
#pragma unroll
        for (int k = 0; k < 64; k++) {
            float vv = sKV[k * 33 + ecol];
#pragma unroll
            for (int i = 0; i < 8; i++)
                oacc[i] += sS[(q0b + i) * 64 + k] * vv;
        }
#pragma unroll
        for (int i = 0; i < 8; i++)
            O[base + (size_t)(q0b + i) * E_DIM + c0 + ecol] = oacc[i];
        __syncthreads();
    }
}

// ====================================================================
// Y = LayerNorm(A + R) * g + b.  SPLIT: also emit fp16 plane.
// ====================================================================
template <bool SPLIT>
__global__ __launch_bounds__(256) void add_ln_kernel(
    const float* __restrict__ A, const float* __restrict__ R,
    const float* __restrict__ g, const float* __restrict__ b,
    float* __restrict__ Y, __half* __restrict__ Yh)
{
    const size_t off = (size_t)blockIdx.x * E_DIM;
    const int tid = threadIdx.x;
    float v[4];
    float s = 0.f, s2 = 0.f;
#pragma unroll
    for (int i = 0; i < 4; i++) {
        int c = tid + i * 256;
        float t = A[off + c] + R[off + c];
        v[i] = t; s += t; s2 += t * t;
    }
#pragma unroll
    for (int o = 16; o > 0; o >>= 1) {
        s  += __shfl_xor_sync(0xffffffffu, s,  o);
        s2 += __shfl_xor_sync(0xffffffffu, s2, o);
    }
    __shared__ float rs[8], rs2[8];
    __shared__ float s_mean, s_rstd;
    const int lane = tid & 31, wrp = tid >> 5;
    if (lane == 0) { rs[wrp] = s; rs2[wrp] = s2; }
    __syncthreads();
    if (tid == 0) {
        float a = 0.f, a2 = 0.f;
#pragma unroll
        for (int i = 0; i < 8; i++) { a += rs[i]; a2 += rs2[i]; }
        float mean = a * (1.0f / E_DIM);
        float var  = a2 * (1.0f / E_DIM) - mean * mean;
        s_mean = mean;
        s_rstd = rsqrtf(var + LN_EPS);
    }
    __syncthreads();
    const float mean = s_mean, rstd = s_rstd;
#pragma unroll
    for (int i = 0; i < 4; i++) {
        int c = tid + i * 256;
        float y = (v[i] - mean) * rstd * g[c] + b[c];
        if (Y) Y[off + c] = y;
        if (SPLIT) Yh[off + c] = __float2half(y);
    }
}

// ====================================================================
extern "C" void kernel_launch(void* const* d_in, const int* in_sizes, int n_in,
                              void* d_out, int out_size)
{
    (void)in_sizes; (void)n_in; (void)out_size;
    const float* x   = (const float*)d_in[0];
    const float* Wq  = (const float*)d_in[1];
    const float* bq  = (const float*)d_in[2];
    const float* Wk  = (const float*)d_in[3];
    const float* bk  = (const float*)d_in[4];
    const float* Wv  = (const float*)d_in[5];
    const float* bv  = (const float*)d_in[6];
    const float* g1  = (const float*)d_in[7];
    const float* be1 = (const float*)d_in[8];
    const float* W1  = (const float*)d_in[9];
    const float* b1  = (const float*)d_in[10];
    const float* W2  = (const float*)d_in[11];
    const float* b2  = (const float*)d_in[12];
    const float* g2  = (const float*)d_in[13];
    const float* be2 = (const float*)d_in[14];
    float* out = (float*)d_out;

    float *q, *k, *v, *att, *x1, *f;
    cudaGetSymbolAddress((void**)&q,   g_q);
    cudaGetSymbolAddress((void**)&k,   g_k);
    cudaGetSymbolAddress((void**)&v,   g_v);
    cudaGetSymbolAddress((void**)&att, g_att);
    cudaGetSymbolAddress((void**)&x1,  g_x1);
    cudaGetSymbolAddress((void**)&f,   g_f);

    __half *xh, *x1h, *hh, *wq, *wk, *wv, *w1, *w2;
    cudaGetSymbolAddress((void**)&xh,  g_xh);
    cudaGetSymbolAddress((void**)&x1h, g_x1h);
    cudaGetSymbolAddress((void**)&hh,  g_hh);
    cudaGetSymbolAddress((void**)&wq,  g_wq);
    cudaGetSymbolAddress((void**)&wk,  g_wk);
    cudaGetSymbolAddress((void**)&wv,  g_wv);
    cudaGetSymbolAddress((void**)&w1,  g_w1);
    cudaGetSymbolAddress((void**)&w2,  g_w2);

    cudaFuncSetAttribute(gemm_tn<0>, cudaFuncAttributeMaxDynamicSharedMemorySize, SMEM_TOTAL);
    cudaFuncSetAttribute(gemm_tn<1>, cudaFuncAttributeMaxDynamicSharedMemorySize, SMEM_TOTAL);

    dim3 blk(256);
    dim3 tblk(32, 8);

    // operand prep
    cvt_kernel<<<(M_TOT * E_DIM / 4 + 255) / 256, blk>>>(x, xh, M_TOT * E_DIM / 4);
    wtrans_kernel<<<dim3(E_DIM / 32, E_DIM / 32), tblk>>>(Wq, wq, E_DIM, E_DIM);
    wtrans_kernel<<<dim3(E_DIM / 32, E_DIM / 32), tblk>>>(Wk, wk, E_DIM, E_DIM);
    wtrans_kernel<<<dim3(E_DIM / 32, E_DIM / 32), tblk>>>(Wv, wv, E_DIM, E_DIM);
    wtrans_kernel<<<dim3(HID_DIM / 32, E_DIM / 32), tblk>>>(W1, w1, E_DIM, HID_DIM);
    wtrans_kernel<<<dim3(E_DIM / 32, HID_DIM / 32), tblk>>>(W2, w2, HID_DIM, E_DIM);

    // QKV projections (tensor core)
    dim3 grid_qkv(E_DIM / BN, M_TOT / BM);       // (8, 128)
    gemm_tn<0><<<grid_qkv, blk, SMEM_TOTAL>>>(xh, wq, bq, q, nullptr, M_TOT, E_DIM, E_DIM);
    gemm_tn<0><<<grid_qkv, blk, SMEM_TOTAL>>>(xh, wk, bk, k, nullptr, M_TOT, E_DIM, E_DIM);
    gemm_tn<0><<<grid_qkv, blk, SMEM_TOTAL>>>(xh, wv, bv, v, nullptr, M_TOT, E_DIM, E_DIM);

    // per-window attention
    attn_kernel<<<NWIN, blk>>>(q, k, v, att);

    // x1 = LN(x + att), emit fp32 + fp16
    add_ln_kernel<true><<<M_TOT, blk>>>(x, att, g1, be1, x1, x1h);

    // FFN1: h = relu(x1 @ W1 + b1), write fp16 h
    dim3 grid_f1(HID_DIM / BN, M_TOT / BM);      // (32, 128)
    gemm_tn<1><<<grid_f1, blk, SMEM_TOTAL>>>(x1h, w1, b1, nullptr, hh, M_TOT, HID_DIM, E_DIM);

    // FFN2: f = h @ W2 + b2 (fp32)
    dim3 grid_f2(E_DIM / BN, M_TOT / BM);        // (8, 128)
    gemm_tn<0><<<grid_f2, blk, SMEM_TOTAL>>>(hh, w2, b2, f, nullptr, M_TOT, E_DIM, HID_DIM);

    // out = LN(x1 + f)
    add_ln_kernel<false><<<M_TOT, blk>>>(x1, f, g2, be2, out, nullptr);
}

// round 8
// speedup vs baseline: 2.7597x; 1.1766x over previous
#include <cuda_runtime.h>
#include <cuda_fp16.h>
#include <math.h>
#include <stdint.h>

#define E_DIM   1024
#define HID_DIM 4096
#define M_TOT   16384          // B*S = 4*4096
#define NWIN    256            // 4*64 windows of 64 tokens
#define SM_SCALE 0.03125f      // 1024^-0.5
#define LN_EPS  1e-5f

// ---- GEMM tiling (mma.sync fp16, single term) ----
#define BM 128
#define BN 128
#define BK 32                  // K elems per stage
#define SROW 40                // padded row length in fp16 elems (80B)
#define PL 10240               // plane bytes (128*40*2)
#define STG 20480              // stage bytes: A + B
#define NSTAGE 4
#define SMEM_TOTAL (NSTAGE*STG)   // 81920

// -------- scratch (device globals; no allocation allowed) --------
__device__ float g_att[M_TOT * E_DIM];
__device__ float g_x1 [M_TOT * E_DIM];
__device__ float g_f  [M_TOT * E_DIM];

__device__ __half g_xh  [M_TOT * E_DIM];
__device__ __half g_x1h [M_TOT * E_DIM];
__device__ __half g_hh  [M_TOT * HID_DIM];
__device__ __half g_qkvh[M_TOT * 3 * E_DIM];

__device__ __half g_wqkv[3 * E_DIM * E_DIM];
__device__ float  g_bqkv[3 * E_DIM];
__device__ __half g_w1 [E_DIM * HID_DIM];
__device__ __half g_w2 [HID_DIM * E_DIM];

// ====================================================================
// helpers
// ====================================================================
__device__ __forceinline__ void mma16816(float* c, const uint32_t* a, const uint32_t* b) {
    asm volatile(
        "mma.sync.aligned.m16n8k16.row.col.f32.f16.f16.f32 "
        "{%0,%1,%2,%3},{%4,%5,%6,%7},{%8,%9},{%0,%1,%2,%3};"
        : "+f"(c[0]), "+f"(c[1]), "+f"(c[2]), "+f"(c[3])
        : "r"(a[0]), "r"(a[1]), "r"(a[2]), "r"(a[3]), "r"(b[0]), "r"(b[1]));
}

__device__ __forceinline__ void ldsm4(uint32_t& r0, uint32_t& r1, uint32_t& r2, uint32_t& r3,
                                      uint32_t addr) {
    asm volatile("ldmatrix.sync.aligned.m8n8.x4.shared.b16 {%0,%1,%2,%3},[%4];"
                 : "=r"(r0), "=r"(r1), "=r"(r2), "=r"(r3) : "r"(addr));
}

__device__ __forceinline__ void ldsm4t(uint32_t& r0, uint32_t& r1, uint32_t& r2, uint32_t& r3,
                                       uint32_t addr) {
    asm volatile("ldmatrix.sync.aligned.m8n8.x4.trans.shared.b16 {%0,%1,%2,%3},[%4];"
                 : "=r"(r0), "=r"(r1), "=r"(r2), "=r"(r3) : "r"(addr));
}

// ====================================================================
// elementwise convert: X fp32 -> fp16
// ====================================================================
__global__ __launch_bounds__(256) void cvt_kernel(
    const float* __restrict__ X, __half* __restrict__ H, int n4)
{
    int i = blockIdx.x * 256 + threadIdx.x;
    if (i >= n4) return;
    float4 v = ((const float4*)X)[i];
    __half2* Hp = (__half2*)(H + (size_t)i * 4);
    Hp[0] = __floats2half2_rn(v.x, v.y);
    Hp[1] = __floats2half2_rn(v.z, v.w);
}

// concat 3 bias vectors of length E_DIM
__global__ void concat_bias_kernel(const float* __restrict__ a, const float* __restrict__ b,
                                   const float* __restrict__ c, float* __restrict__ o)
{
    int i = blockIdx.x * 256 + threadIdx.x;
    if (i >= 3 * E_DIM) return;
    o[i] = (i < E_DIM) ? a[i] : (i < 2 * E_DIM ? b[i - E_DIM] : c[i - 2 * E_DIM]);
}

// ====================================================================
// weight transpose: W[K,N] fp32 -> T[N,K] fp16
// ====================================================================
__global__ __launch_bounds__(256) void wtrans_kernel(
    const float* __restrict__ W, __half* __restrict__ T, int K, int N)
{
    __shared__ float t[32][33];
    const int tx = threadIdx.x, ty = threadIdx.y;
    const int n0 = blockIdx.x * 32, k0 = blockIdx.y * 32;
#pragma unroll
    for (int i = ty; i < 32; i += 8)
        t[i][tx] = W[(size_t)(k0 + i) * N + n0 + tx];
    __syncthreads();
#pragma unroll
    for (int i = ty; i < 32; i += 8)
        T[(size_t)(n0 + i) * K + k0 + tx] = __float2half(t[tx][i]);
}

// ====================================================================
// GEMM (TN): C[M,N] = A[M,K] @ B[N,K]^T + bias   (fp16 x fp16 -> fp32)
//   EPI=0: C fp32.  EPI=1: relu + fp16 Ch.  EPI=2: fp16 Ch only.
// ====================================================================
template <int EPI>
__global__ __launch_bounds__(256, 2) void gemm_tn(
    const __half* __restrict__ A, const __half* __restrict__ B,
    const float* __restrict__ bias,
    float* __restrict__ C, __half* __restrict__ Ch,
    int M, int N, int K)
{
    extern __shared__ __align__(16) char smem_raw[];
    const int tid = threadIdx.x;
    const int bm0 = blockIdx.y * BM;
    const int bn0 = blockIdx.x * BN;
    const int lane = tid & 31, w = tid >> 5;
    const int g = lane >> 2, q4 = lane & 3;
    const int wm = (w >> 2) * 64;
    const int wn = (w & 3) * 32;

    const uint32_t sbase = (uint32_t)__cvta_generic_to_shared(smem_raw);

    const uint32_t aoff = (uint32_t)((wm + (lane & 15)) * (SROW * 2) + (lane >> 4) * 16);
    const uint32_t boff = (uint32_t)((wn + (lane >> 4) * 8 + (lane & 7)) * (SROW * 2)
                                     + ((lane >> 3) & 1) * 16);

    float acc[4][4][4];
#pragma unroll
    for (int i = 0; i < 4; i++)
#pragma unroll
        for (int j = 0; j < 4; j++)
#pragma unroll
            for (int r = 0; r < 4; r++) acc[i][j][r] = 0.f;

    const __half* gp[2] = {A, B};
    const int rb[2] = {bm0, bn0};

    auto load_stage = [&](int s, int k0) {
        uint32_t sb = sbase + s * STG;
#pragma unroll
        for (int p = 0; p < 2; p++) {
#pragma unroll
            for (int t = 0; t < 2; t++) {
                int c = tid + t * 256;
                int row = c >> 2, cc = c & 3;
                uint32_t sa = sb + p * PL + (uint32_t)(row * SROW + cc * 8) * 2;
                const void* gptr = gp[p] + (size_t)(rb[p] + row) * K + k0 + cc * 8;
                asm volatile("cp.async.cg.shared.global [%0],[%1],16;" :: "r"(sa), "l"(gptr));
            }
        }
        asm volatile("cp.async.commit_group;");
    };

    const int KT = K / BK;
    load_stage(0, 0);
    load_stage(1, BK);
    load_stage(2, 2 * BK);

    for (int kt = 0; kt < KT; kt++) {
        const int s = kt % NSTAGE;
        if (kt < KT - 2)       asm volatile("cp.async.wait_group 2;");
        else if (kt == KT - 2) asm volatile("cp.async.wait_group 1;");
        else                   asm volatile("cp.async.wait_group 0;");
        __syncthreads();
        if (kt + 3 < KT) load_stage((kt + 3) % NSTAGE, (kt + 3) * BK);

        const uint32_t stg = sbase + s * STG;

#pragma unroll
        for (int ks = 0; ks < 2; ks++) {
            const uint32_t ka = stg + ks * 32 + aoff;
            const uint32_t kb = stg + PL + ks * 32 + boff;

            uint32_t bfr[4][2];
            ldsm4(bfr[0][0], bfr[0][1], bfr[1][0], bfr[1][1], kb);
            ldsm4(bfr[2][0], bfr[2][1], bfr[3][0], bfr[3][1], kb + 16 * (SROW * 2));

            uint32_t afr[4][4];
#pragma unroll
            for (int tm = 0; tm < 4; tm++)
                ldsm4(afr[tm][0], afr[tm][1], afr[tm][2], afr[tm][3], ka + tm * 16 * (SROW * 2));

#pragma unroll
            for (int tm = 0; tm < 4; tm++)
#pragma unroll
                for (int tn = 0; tn < 4; tn++)
                    mma16816(acc[tm][tn], afr[tm], bfr[tn]);
        }
    }

    // epilogue
#pragma unroll
    for (int tm = 0; tm < 4; tm++) {
#pragma unroll
        for (int tn = 0; tn < 4; tn++) {
            int r0 = bm0 + wm + tm * 16 + g;
            int col = bn0 + wn + tn * 8 + q4 * 2;
            float b0 = bias[col], b1 = bias[col + 1];
            float v00 = acc[tm][tn][0] + b0, v01 = acc[tm][tn][1] + b1;
            float v10 = acc[tm][tn][2] + b0, v11 = acc[tm][tn][3] + b1;
            if (EPI == 0) {
                *(float2*)(C + (size_t)r0 * N + col) = make_float2(v00, v01);
                *(float2*)(C + (size_t)(r0 + 8) * N + col) = make_float2(v10, v11);
            } else {
                if (EPI == 1) {
                    v00 = fmaxf(v00, 0.f); v01 = fmaxf(v01, 0.f);
                    v10 = fmaxf(v10, 0.f); v11 = fmaxf(v11, 0.f);
                }
                *(__half2*)(Ch + (size_t)r0 * N + col)       = __floats2half2_rn(v00, v01);
                *(__half2*)(Ch + (size_t)(r0 + 8) * N + col) = __floats2half2_rn(v10, v11);
            }
        }
    }
}

// ====================================================================
// MMA window attention: one block per 64-token window.
// QKV fp16 [M,3072] (q|k|v per row). O fp32 [M,1024].
// ====================================================================
#define ASROW 72               // smem row length (fp16 elems) for Q/K/V/P tiles
#define ASROWB 144             // bytes
#define SSROW 68               // fp32 score row stride

__global__ __launch_bounds__(256) void attn_mma_kernel(
    const __half* __restrict__ QKV, float* __restrict__ O)
{
    __shared__ __half sQ[64 * ASROW];
    __shared__ __half sK[64 * ASROW];   // reused for V in phase 3
    __shared__ float  sS[64 * SSROW];
    __shared__ __half sP[64 * ASROW];

    const int tid = threadIdx.x;
    const int lane = tid & 31, w = tid >> 5;
    const int tok0 = blockIdx.x * 64;
    const int m0 = (w >> 1) * 16;       // 0,16,32,48
    const int n0 = (w & 1) * 32;        // 0,32
    const int g = lane >> 2, q4 = lane & 3;

    const uint32_t sQb = (uint32_t)__cvta_generic_to_shared(sQ);
    const uint32_t sKb = (uint32_t)__cvta_generic_to_shared(sK);
    const uint32_t sPb = (uint32_t)__cvta_generic_to_shared(sP);

    const uint32_t aoff = (uint32_t)((m0 + (lane & 15)) * ASROWB + (lane >> 4) * 16);
    const uint32_t boff = (uint32_t)((n0 + (lane >> 4) * 8 + (lane & 7)) * ASROWB
                                     + ((lane >> 3) & 1) * 16);
    // trans B (V): row = k token, col = n
    const uint32_t toff = (uint32_t)((lane & 15) * ASROWB + n0 * 2 + (lane >> 4) * 16);

    // loader: 64 rows x 64 halves (128B) per tile; 512 16B-chunks, 2/thread
    auto load_tile = [&](uint32_t dstb, __half* dst, int seg, int c0) {
#pragma unroll
        for (int t = 0; t < 2; t++) {
            int i = tid + t * 256;
            int row = i >> 3, cc = i & 7;
            const uint4* src = (const uint4*)(QKV + (size_t)(tok0 + row) * 3072 + seg + c0 + cc * 8);
            *(uint4*)((char*)dst + row * ASROWB + cc * 16) = *src;
        }
        (void)dstb;
    };

    // ---- phase 1: S = Q K^T ----
    float accs[4][4];
#pragma unroll
    for (int i = 0; i < 4; i++)
#pragma unroll
        for (int r = 0; r < 4; r++) accs[i][r] = 0.f;

    for (int c0 = 0; c0 < E_DIM; c0 += 64) {
        load_tile(sQb, sQ, 0, c0);
        load_tile(sKb, sK, E_DIM, c0);
        __syncthreads();
#pragma unroll
        for (int ks = 0; ks < 4; ks++) {
            uint32_t afr[4], bfr[4][2];
            ldsm4(afr[0], afr[1], afr[2], afr[3], sQb + ks * 32 + aoff);
            ldsm4(bfr[0][0], bfr[0][1], bfr[1][0], bfr[1][1], sKb + ks * 32 + boff);
            ldsm4(bfr[2][0], bfr[2][1], bfr[3][0], bfr[3][1], sKb + ks * 32 + boff + 16 * ASROWB);
#pragma unroll
            for (int tn = 0; tn < 4; tn++)
                mma16816(accs[tn], afr, bfr[tn]);
        }
        __syncthreads();
    }

    // write scaled scores
#pragma unroll
    for (int tn = 0; tn < 4; tn++) {
        int col = n0 + tn * 8 + q4 * 2;
        *(float2*)(&sS[(m0 + g) * SSROW + col])     = make_float2(accs[tn][0] * SM_SCALE, accs[tn][1] * SM_SCALE);
        *(float2*)(&sS[(m0 + g + 8) * SSROW + col]) = make_float2(accs[tn][2] * SM_SCALE, accs[tn][3] * SM_SCALE);
    }
    __syncthreads();

    // ---- phase 2: softmax over rows ----
    {
        const int r = w * 8 + (lane >> 2);   // unused: keep per-warp-8row scheme below
        (void)r;
    }
    for (int r = w * 8; r < w * 8 + 8; r++) {
        float v0 = sS[r * SSROW + lane];
        float v1 = sS[r * SSROW + 32 + lane];
        float m = fmaxf(v0, v1);
#pragma unroll
        for (int o = 16; o > 0; o >>= 1)
            m = fmaxf(m, __shfl_xor_sync(0xffffffffu, m, o));
        float e0 = __expf(v0 - m), e1 = __expf(v1 - m);
        float s = e0 + e1;
#pragma unroll
        for (int o = 16; o > 0; o >>= 1)
            s += __shfl_xor_sync(0xffffffffu, s, o);
        float inv = 1.0f / s;
        sS[r * SSROW + lane]      = e0 * inv;
        sS[r * SSROW + 32 + lane] = e1 * inv;
    }
    __syncthreads();

    // convert P to fp16
#pragma unroll
    for (int i = 0; i < 16; i++) {
        int flat = tid * 16 + i;
        int r = flat >> 6, c = flat & 63;
        sP[r * ASROW + c] = __float2half(sS[r * SSROW + c]);
    }
    __syncthreads();

    // ---- phase 3: O = P @ V ----
    for (int c0 = 0; c0 < E_DIM; c0 += 64) {
        load_tile(sKb, sK, 2 * E_DIM, c0);   // V chunk into sK
        __syncthreads();
        float acco[4][4];
#pragma unroll
        for (int i = 0; i < 4; i++)
#pragma unroll
            for (int r = 0; r < 4; r++) acco[i][r] = 0.f;
#pragma unroll
        for (int ks = 0; ks < 4; ks++) {
            uint32_t afr[4], bfr[4][2];
            ldsm4(afr[0], afr[1], afr[2], afr[3], sPb + ks * 32 + aoff);
            uint32_t base = sKb + (uint32_t)(ks * 16) * ASROWB + toff;
            ldsm4t(bfr[0][0], bfr[0][1], bfr[1][0], bfr[1][1], base);
            ldsm4t(bfr[2][0], bfr[2][1], bfr[3][0], bfr[3][1], base + 32);  // +16 cols
#pragma unroll
            for (int tn = 0; tn < 4; tn++)
                mma16816(acco[tn], afr, bfr[tn]);
        }
#pragma unroll
        for (int tn = 0; tn < 4; tn++) {
            int col = c0 + n0 + tn * 8 + q4 * 2;
            *(float2*)(O + (size_t)(tok0 + m0 + g) * E_DIM + col)     = make_float2(acco[tn][0], acco[tn][1]);
            *(float2*)(O + (size_t)(tok0 + m0 + g + 8) * E_DIM + col) = make_float2(acco[tn][2], acco[tn][3]);
        }
        __syncthreads();
    }
}

// ====================================================================
// Y = LayerNorm(A + R) * g + b.  SPLIT: also emit fp16 plane.
// ====================================================================
template <bool SPLIT>
__global__ __launch_bounds__(256) void add_ln_kernel(
    const float* __restrict__ A, const float* __restrict__ R,
    const float* __restrict__ g, const float* __restrict__ b,
    float* __restrict__ Y, __half* __restrict__ Yh)
{
    const size_t off = (size_t)blockIdx.x * E_DIM;
    const int tid = threadIdx.x;
    float v[4];
    float s = 0.f, s2 = 0.f;
#pragma unroll
    for (int i = 0; i < 4; i++) {
        int c = tid + i * 256;
        float t = A[off + c] + R[off + c];
        v[i] = t; s += t; s2 += t * t;
    }
#pragma unroll
    for (int o = 16; o > 0; o >>= 1) {
        s  += __shfl_xor_sync(0xffffffffu, s,  o);
        s2 += __shfl_xor_sync(0xffffffffu, s2, o);
    }
    __shared__ float rs[8], rs2[8];
    __shared__ float s_mean, s_rstd;
    const int lane = tid & 31, wrp = tid >> 5;
    if (lane == 0) { rs[wrp] = s; rs2[wrp] = s2; }
    __syncthreads();
    if (tid == 0) {
        float a = 0.f, a2 = 0.f;
#pragma unroll
        for (int i = 0; i < 8; i++) { a += rs[i]; a2 += rs2[i]; }
        float mean = a * (1.0f / E_DIM);
        float var  = a2 * (1.0f / E_DIM) - mean * mean;
        s_mean = mean;
        s_rstd = rsqrtf(var + LN_EPS);
    }
    __syncthreads();
    const float mean = s_mean, rstd = s_rstd;
#pragma unroll
    for (int i = 0; i < 4; i++) {
        int c = tid + i * 256;
        float y = (v[i] - mean) * rstd * g[c] + b[c];
        if (Y) Y[off + c] = y;
        if (SPLIT) Yh[off + c] = __float2half(y);
    }
}

// ====================================================================
extern "C" void kernel_launch(void* const* d_in, const int* in_sizes, int n_in,
                              void* d_out, int out_size)
{
    (void)in_sizes; (void)n_in; (void)out_size;
    const float* x   = (const float*)d_in[0];
    const float* Wq  = (const float*)d_in[1];
    const float* bq  = (const float*)d_in[2];
    const float* Wk  = (const float*)d_in[3];
    const float* bk  = (const float*)d_in[4];
    const float* Wv  = (const float*)d_in[5];
    const float* bv  = (const float*)d_in[6];
    const float* g1  = (const float*)d_in[7];
    const float* be1 = (const float*)d_in[8];
    const float* W1  = (const float*)d_in[9];
    const float* b1  = (const float*)d_in[10];
    const float* W2  = (const float*)d_in[11];
    const float* b2  = (const float*)d_in[12];
    const float* g2  = (const float*)d_in[13];
    const float* be2 = (const float*)d_in[14];
    float* out = (float*)d_out;

    float *att, *x1, *f, *bqkv;
    cudaGetSymbolAddress((void**)&att,  g_att);
    cudaGetSymbolAddress((void**)&x1,   g_x1);
    cudaGetSymbolAddress((void**)&f,    g_f);
    cudaGetSymbolAddress((void**)&bqkv, g_bqkv);

    __half *xh, *x1h, *hh, *qkvh, *wqkv, *w1, *w2;
    cudaGetSymbolAddress((void**)&xh,   g_xh);
    cudaGetSymbolAddress((void**)&x1h,  g_x1h);
    cudaGetSymbolAddress((void**)&hh,   g_hh);
    cudaGetSymbolAddress((void**)&qkvh, g_qkvh);
    cudaGetSymbolAddress((void**)&wqkv, g_wqkv);
    cudaGetSymbolAddress((void**)&w1,   g_w1);
    cudaGetSymbolAddress((void**)&w2,   g_w2);

    cudaFuncSetAttribute(gemm_tn<0>, cudaFuncAttributeMaxDynamicSharedMemorySize, SMEM_TOTAL);
    cudaFuncSetAttribute(gemm_tn<1>, cudaFuncAttributeMaxDynamicSharedMemorySize, SMEM_TOTAL);
    cudaFuncSetAttribute(gemm_tn<2>, cudaFuncAttributeMaxDynamicSharedMemorySize, SMEM_TOTAL);

    dim3 blk(256);
    dim3 tblk(32, 8);

    // operand prep
    cvt_kernel<<<(M_TOT * E_DIM / 4 + 255) / 256, blk>>>(x, xh, M_TOT * E_DIM / 4);
    wtrans_kernel<<<dim3(E_DIM / 32, E_DIM / 32), tblk>>>(Wq, wqkv,                    E_DIM, E_DIM);
    wtrans_kernel<<<dim3(E_DIM / 32, E_DIM / 32), tblk>>>(Wk, wqkv + E_DIM * E_DIM,     E_DIM, E_DIM);
    wtrans_kernel<<<dim3(E_DIM / 32, E_DIM / 32), tblk>>>(Wv, wqkv + 2 * E_DIM * E_DIM, E_DIM, E_DIM);
    concat_bias_kernel<<<(3 * E_DIM + 255) / 256, blk>>>(bq, bk, bv, bqkv);
    wtrans_kernel<<<dim3(HID_DIM / 32, E_DIM / 32), tblk>>>(W1, w1, E_DIM, HID_DIM);
    wtrans_kernel<<<dim3(E_DIM / 32, HID_DIM / 32), tblk>>>(W2, w2, HID_DIM, E_DIM);

    // fused QKV projection -> fp16 [M, 3072]
    dim3 grid_qkv(3 * E_DIM / BN, M_TOT / BM);   // (24, 128)
    gemm_tn<2><<<grid_qkv, blk, SMEM_TOTAL>>>(xh, wqkv, bqkv, nullptr, qkvh, M_TOT, 3 * E_DIM, E_DIM);

    // per-window MMA attention
    attn_mma_kernel<<<NWIN, blk>>>(qkvh, att);

    // x1 = LN(x + att), emit fp32 + fp16
    add_ln_kernel<true><<<M_TOT, blk>>>(x, att, g1, be1, x1, x1h);

    // FFN1: h = relu(x1 @ W1 + b1), write fp16 h
    dim3 grid_f1(HID_DIM / BN, M_TOT / BM);      // (32, 128)
    gemm_tn<1><<<grid_f1, blk, SMEM_TOTAL>>>(x1h, w1, b1, nullptr, hh, M_TOT, HID_DIM, E_DIM);

    // FFN2: f = h @ W2 + b2 (fp32)
    dim3 grid_f2(E_DIM / BN, M_TOT / BM);        // (8, 128)
    gemm_tn<0><<<grid_f2, blk, SMEM_TOTAL>>>(hh, w2, b2, f, nullptr, M_TOT, E_DIM, HID_DIM);

    // out = LN(x1 + f)
    add_ln_kernel<false><<<M_TOT, blk>>>(x1, f, g2, be2, out, nullptr);
}

// round 9
// speedup vs baseline: 3.0695x; 1.1122x over previous
#include <cuda_runtime.h>
#include <cuda_fp16.h>
#include <math.h>
#include <stdint.h>

#define E_DIM   1024
#define HID_DIM 4096
#define M_TOT   16384          // B*S = 4*4096
#define NWIN    256            // 4*64 windows of 64 tokens
#define SM_SCALE 0.03125f      // 1024^-0.5
#define LN_EPS  1e-5f

// ---- GEMM tiling (mma.sync fp16, single term), BK=64 ----
#define BM 128
#define BN 128
#define BK 64                  // K elems per stage
#define SROW 72                // padded row length in fp16 elems (144B)
#define PL 18432               // plane bytes (128*72*2)
#define STG 36864              // stage bytes: A + B
#define NSTAGE 3
#define SMEM_TOTAL (NSTAGE*STG)   // 110592

// -------- scratch (device globals; no allocation allowed) --------
__device__ float g_att[M_TOT * E_DIM];
__device__ float g_x1 [M_TOT * E_DIM];
__device__ float g_f  [M_TOT * E_DIM];

__device__ __half g_xh  [M_TOT * E_DIM];
__device__ __half g_x1h [M_TOT * E_DIM];
__device__ __half g_hh  [M_TOT * HID_DIM];
__device__ __half g_qkvh[M_TOT * 3 * E_DIM];

__device__ __half g_wqkv[3 * E_DIM * E_DIM];
__device__ float  g_bqkv[3 * E_DIM];
__device__ __half g_w1 [E_DIM * HID_DIM];
__device__ __half g_w2 [HID_DIM * E_DIM];

// ====================================================================
// helpers
// ====================================================================
__device__ __forceinline__ void mma16816(float* c, const uint32_t* a, const uint32_t* b) {
    asm volatile(
        "mma.sync.aligned.m16n8k16.row.col.f32.f16.f16.f32 "
        "{%0,%1,%2,%3},{%4,%5,%6,%7},{%8,%9},{%0,%1,%2,%3};"
        : "+f"(c[0]), "+f"(c[1]), "+f"(c[2]), "+f"(c[3])
        : "r"(a[0]), "r"(a[1]), "r"(a[2]), "r"(a[3]), "r"(b[0]), "r"(b[1]));
}

__device__ __forceinline__ void ldsm4(uint32_t& r0, uint32_t& r1, uint32_t& r2, uint32_t& r3,
                                      uint32_t addr) {
    asm volatile("ldmatrix.sync.aligned.m8n8.x4.shared.b16 {%0,%1,%2,%3},[%4];"
                 : "=r"(r0), "=r"(r1), "=r"(r2), "=r"(r3) : "r"(addr));
}

__device__ __forceinline__ void ldsm4t(uint32_t& r0, uint32_t& r1, uint32_t& r2, uint32_t& r3,
                                       uint32_t addr) {
    asm volatile("ldmatrix.sync.aligned.m8n8.x4.trans.shared.b16 {%0,%1,%2,%3},[%4];"
                 : "=r"(r0), "=r"(r1), "=r"(r2), "=r"(r3) : "r"(addr));
}

// ====================================================================
// elementwise convert: X fp32 -> fp16
// ====================================================================
__global__ __launch_bounds__(256) void cvt_kernel(
    const float* __restrict__ X, __half* __restrict__ H, int n4)
{
    int i = blockIdx.x * 256 + threadIdx.x;
    if (i >= n4) return;
    float4 v = ((const float4*)X)[i];
    __half2* Hp = (__half2*)(H + (size_t)i * 4);
    Hp[0] = __floats2half2_rn(v.x, v.y);
    Hp[1] = __floats2half2_rn(v.z, v.w);
}

// concat 3 bias vectors of length E_DIM
__global__ void concat_bias_kernel(const float* __restrict__ a, const float* __restrict__ b,
                                   const float* __restrict__ c, float* __restrict__ o)
{
    int i = blockIdx.x * 256 + threadIdx.x;
    if (i >= 3 * E_DIM) return;
    o[i] = (i < E_DIM) ? a[i] : (i < 2 * E_DIM ? b[i - E_DIM] : c[i - 2 * E_DIM]);
}

// ====================================================================
// weight transpose: W[K,N] fp32 -> T[N,K] fp16
// ====================================================================
__global__ __launch_bounds__(256) void wtrans_kernel(
    const float* __restrict__ W, __half* __restrict__ T, int K, int N)
{
    __shared__ float t[32][33];
    const int tx = threadIdx.x, ty = threadIdx.y;
    const int n0 = blockIdx.x * 32, k0 = blockIdx.y * 32;
#pragma unroll
    for (int i = ty; i < 32; i += 8)
        t[i][tx] = W[(size_t)(k0 + i) * N + n0 + tx];
    __syncthreads();
#pragma unroll
    for (int i = ty; i < 32; i += 8)
        T[(size_t)(n0 + i) * K + k0 + tx] = __float2half(t[tx][i]);
}

// ====================================================================
// GEMM (TN): C[M,N] = A[M,K] @ B[N,K]^T + bias   (fp16 x fp16 -> fp32)
//   128x128x64 tiles, 8 warps of 64x32, 3-stage cp.async pipeline.
//   EPI=0: C fp32.  EPI=1: relu + fp16 Ch.  EPI=2: fp16 Ch only.
// ====================================================================
template <int EPI>
__global__ __launch_bounds__(256, 2) void gemm_tn(
    const __half* __restrict__ A, const __half* __restrict__ B,
    const float* __restrict__ bias,
    float* __restrict__ C, __half* __restrict__ Ch,
    int M, int N, int K)
{
    extern __shared__ __align__(16) char smem_raw[];
    const int tid = threadIdx.x;
    const int bm0 = blockIdx.y * BM;
    const int bn0 = blockIdx.x * BN;
    const int lane = tid & 31, w = tid >> 5;
    const int g = lane >> 2, q4 = lane & 3;
    const int wm = (w >> 2) * 64;
    const int wn = (w & 3) * 32;

    const uint32_t sbase = (uint32_t)__cvta_generic_to_shared(smem_raw);

    const uint32_t aoff = (uint32_t)((wm + (lane & 15)) * (SROW * 2) + (lane >> 4) * 16);
    const uint32_t boff = (uint32_t)((wn + (lane >> 4) * 8 + (lane & 7)) * (SROW * 2)
                                     + ((lane >> 3) & 1) * 16);

    float acc[4][4][4];
#pragma unroll
    for (int i = 0; i < 4; i++)
#pragma unroll
        for (int j = 0; j < 4; j++)
#pragma unroll
            for (int r = 0; r < 4; r++) acc[i][j][r] = 0.f;

    const __half* gp[2] = {A, B};
    const int rb[2] = {bm0, bn0};

    auto load_stage = [&](int s, int k0) {
        uint32_t sb = sbase + s * STG;
#pragma unroll
        for (int p = 0; p < 2; p++) {
#pragma unroll
            for (int t = 0; t < 4; t++) {
                int i = tid + t * 256;             // 0..1023
                int row = i >> 3, cc = i & 7;
                uint32_t sa = sb + p * PL + (uint32_t)(row * SROW + cc * 8) * 2;
                const void* gptr = gp[p] + (size_t)(rb[p] + row) * K + k0 + cc * 8;
                asm volatile("cp.async.cg.shared.global [%0],[%1],16;" :: "r"(sa), "l"(gptr));
            }
        }
        asm volatile("cp.async.commit_group;");
    };

    const int KT = K / BK;
    load_stage(0, 0);
    load_stage(1, BK);

    for (int kt = 0; kt < KT; kt++) {
        const int s = kt % NSTAGE;
        if (kt < KT - 1) asm volatile("cp.async.wait_group 1;");
        else             asm volatile("cp.async.wait_group 0;");
        __syncthreads();
        if (kt + 2 < KT) load_stage((kt + 2) % NSTAGE, (kt + 2) * BK);

        const uint32_t stg = sbase + s * STG;

#pragma unroll
        for (int ks = 0; ks < 4; ks++) {
            const uint32_t ka = stg + ks * 32 + aoff;
            const uint32_t kb = stg + PL + ks * 32 + boff;

            uint32_t bfr[4][2];
            ldsm4(bfr[0][0], bfr[0][1], bfr[1][0], bfr[1][1], kb);
            ldsm4(bfr[2][0], bfr[2][1], bfr[3][0], bfr[3][1], kb + 16 * (SROW * 2));

            uint32_t afr[4][4];
#pragma unroll
            for (int tm = 0; tm < 4; tm++)
                ldsm4(afr[tm][0], afr[tm][1], afr[tm][2], afr[tm][3], ka + tm * 16 * (SROW * 2));

#pragma unroll
            for (int tm = 0; tm < 4; tm++)
#pragma unroll
                for (int tn = 0; tn < 4; tn++)
                    mma16816(acc[tm][tn], afr[tm], bfr[tn]);
        }
    }

    // epilogue
#pragma unroll
    for (int tm = 0; tm < 4; tm++) {
#pragma unroll
        for (int tn = 0; tn < 4; tn++) {
            int r0 = bm0 + wm + tm * 16 + g;
            int col = bn0 + wn + tn * 8 + q4 * 2;
            float b0 = bias[col], b1 = bias[col + 1];
            float v00 = acc[tm][tn][0] + b0, v01 = acc[tm][tn][1] + b1;
            float v10 = acc[tm][tn][2] + b0, v11 = acc[tm][tn][3] + b1;
            if (EPI == 0) {
                *(float2*)(C + (size_t)r0 * N + col) = make_float2(v00, v01);
                *(float2*)(C + (size_t)(r0 + 8) * N + col) = make_float2(v10, v11);
            } else {
                if (EPI == 1) {
                    v00 = fmaxf(v00, 0.f); v01 = fmaxf(v01, 0.f);
                    v10 = fmaxf(v10, 0.f); v11 = fmaxf(v11, 0.f);
                }
                *(__half2*)(Ch + (size_t)r0 * N + col)       = __floats2half2_rn(v00, v01);
                *(__half2*)(Ch + (size_t)(r0 + 8) * N + col) = __floats2half2_rn(v10, v11);
            }
        }
    }
}

// ====================================================================
// MMA window attention, cp.async double-buffered.
// QKV fp16 [M,3072] (q|k|v per row). O fp32 [M,1024].
// ====================================================================
#define ASROW 72               // smem row length (fp16 elems)
#define ASROWB 144             // bytes
#define SSROW 68               // fp32 score row stride
#define NCH 16                 // 1024/64 chunks

__global__ __launch_bounds__(256) void attn_mma_kernel(
    const __half* __restrict__ QKV, float* __restrict__ O)
{
    __shared__ __half sQ[2 * 64 * ASROW];
    __shared__ __half sK[2 * 64 * ASROW];   // reused for V in phase 3
    __shared__ float  sS[64 * SSROW];
    __shared__ __half sP[64 * ASROW];

    const int tid = threadIdx.x;
    const int lane = tid & 31, w = tid >> 5;
    const int tok0 = blockIdx.x * 64;
    const int m0 = (w >> 1) * 16;       // 0,16,32,48
    const int n0 = (w & 1) * 32;        // 0,32
    const int g = lane >> 2, q4 = lane & 3;

    const uint32_t sQb = (uint32_t)__cvta_generic_to_shared(sQ);
    const uint32_t sKb = (uint32_t)__cvta_generic_to_shared(sK);
    const uint32_t sPb = (uint32_t)__cvta_generic_to_shared(sP);
    const uint32_t TILE = 64 * ASROWB;

    const uint32_t aoff = (uint32_t)((m0 + (lane & 15)) * ASROWB + (lane >> 4) * 16);
    const uint32_t boff = (uint32_t)((n0 + (lane >> 4) * 8 + (lane & 7)) * ASROWB
                                     + ((lane >> 3) & 1) * 16);
    const uint32_t toff = (uint32_t)((lane & 15) * ASROWB + n0 * 2 + (lane >> 4) * 16);

    // cp.async one 64x64 fp16 tile (512 16B chunks, 2/thread)
    auto cpa_tile = [&](uint32_t dstb, int seg, int c0) {
#pragma unroll
        for (int t = 0; t < 2; t++) {
            int i = tid + t * 256;
            int row = i >> 3, cc = i & 7;
            uint32_t sa = dstb + (uint32_t)(row * ASROWB + cc * 16);
            const void* src = QKV + (size_t)(tok0 + row) * 3072 + seg + c0 + cc * 8;
            asm volatile("cp.async.cg.shared.global [%0],[%1],16;" :: "r"(sa), "l"(src));
        }
    };

    // ---- phase 1: S = Q K^T ----
    float accs[4][4];
#pragma unroll
    for (int i = 0; i < 4; i++)
#pragma unroll
        for (int r = 0; r < 4; r++) accs[i][r] = 0.f;

    cpa_tile(sQb, 0, 0);
    cpa_tile(sKb, E_DIM, 0);
    asm volatile("cp.async.commit_group;");

    for (int c = 0; c < NCH; c++) {
        const uint32_t qb = sQb + (c & 1) * TILE;
        const uint32_t kb = sKb + (c & 1) * TILE;
        if (c + 1 < NCH) {
            cpa_tile(sQb + ((c + 1) & 1) * TILE, 0, (c + 1) * 64);
            cpa_tile(sKb + ((c + 1) & 1) * TILE, E_DIM, (c + 1) * 64);
            asm volatile("cp.async.commit_group;");
            asm volatile("cp.async.wait_group 1;");
        } else {
            asm volatile("cp.async.wait_group 0;");
        }
        __syncthreads();
#pragma unroll
        for (int ks = 0; ks < 4; ks++) {
            uint32_t afr[4], bfr[4][2];
            ldsm4(afr[0], afr[1], afr[2], afr[3], qb + ks * 32 + aoff);
            ldsm4(bfr[0][0], bfr[0][1], bfr[1][0], bfr[1][1], kb + ks * 32 + boff);
            ldsm4(bfr[2][0], bfr[2][1], bfr[3][0], bfr[3][1], kb + ks * 32 + boff + 16 * ASROWB);
#pragma unroll
            for (int tn = 0; tn < 4; tn++)
                mma16816(accs[tn], afr, bfr[tn]);
        }
        __syncthreads();
    }

    // write scaled scores
#pragma unroll
    for (int tn = 0; tn < 4; tn++) {
        int col = n0 + tn * 8 + q4 * 2;
        *(float2*)(&sS[(m0 + g) * SSROW + col])     = make_float2(accs[tn][0] * SM_SCALE, accs[tn][1] * SM_SCALE);
        *(float2*)(&sS[(m0 + g + 8) * SSROW + col]) = make_float2(accs[tn][2] * SM_SCALE, accs[tn][3] * SM_SCALE);
    }
    __syncthreads();

    // ---- phase 2: softmax over rows ----
    for (int r = w * 8; r < w * 8 + 8; r++) {
        float v0 = sS[r * SSROW + lane];
        float v1 = sS[r * SSROW + 32 + lane];
        float m = fmaxf(v0, v1);
#pragma unroll
        for (int o = 16; o > 0; o >>= 1)
            m = fmaxf(m, __shfl_xor_sync(0xffffffffu, m, o));
        float e0 = __expf(v0 - m), e1 = __expf(v1 - m);
        float s = e0 + e1;
#pragma unroll
        for (int o = 16; o > 0; o >>= 1)
            s += __shfl_xor_sync(0xffffffffu, s, o);
        float inv = 1.0f / s;
        sS[r * SSROW + lane]      = e0 * inv;
        sS[r * SSROW + 32 + lane] = e1 * inv;
    }
    __syncthreads();

    // convert P to fp16
#pragma unroll
    for (int i = 0; i < 16; i++) {
        int flat = tid * 16 + i;
        int r = flat >> 6, cc = flat & 63;
        sP[r * ASROW + cc] = __float2half(sS[r * SSROW + cc]);
    }
    __syncthreads();

    // ---- phase 3: O = P @ V ----
    cpa_tile(sKb, 2 * E_DIM, 0);
    asm volatile("cp.async.commit_group;");

    for (int c = 0; c < NCH; c++) {
        const uint32_t vb = sKb + (c & 1) * TILE;
        if (c + 1 < NCH) {
            cpa_tile(sKb + ((c + 1) & 1) * TILE, 2 * E_DIM, (c + 1) * 64);
            asm volatile("cp.async.commit_group;");
            asm volatile("cp.async.wait_group 1;");
        } else {
            asm volatile("cp.async.wait_group 0;");
        }
        __syncthreads();
        float acco[4][4];
#pragma unroll
        for (int i = 0; i < 4; i++)
#pragma unroll
            for (int r = 0; r < 4; r++) acco[i][r] = 0.f;
#pragma unroll
        for (int ks = 0; ks < 4; ks++) {
            uint32_t afr[4], bfr[4][2];
            ldsm4(afr[0], afr[1], afr[2], afr[3], sPb + ks * 32 + aoff);
            uint32_t base = vb + (uint32_t)(ks * 16) * ASROWB + toff;
            ldsm4t(bfr[0][0], bfr[0][1], bfr[1][0], bfr[1][1], base);
            ldsm4t(bfr[2][0], bfr[2][1], bfr[3][0], bfr[3][1], base + 32);
#pragma unroll
            for (int tn = 0; tn < 4; tn++)
                mma16816(acco[tn], afr, bfr[tn]);
        }
#pragma unroll
        for (int tn = 0; tn < 4; tn++) {
            int col = c * 64 + n0 + tn * 8 + q4 * 2;
            *(float2*)(O + (size_t)(tok0 + m0 + g) * E_DIM + col)     = make_float2(acco[tn][0], acco[tn][1]);
            *(float2*)(O + (size_t)(tok0 + m0 + g + 8) * E_DIM + col) = make_float2(acco[tn][2], acco[tn][3]);
        }
        __syncthreads();
    }
}

// ====================================================================
// Y = LayerNorm(A + R) * g + b.  SPLIT: also emit fp16 plane.
// ====================================================================
template <bool SPLIT>
__global__ __launch_bounds__(256) void add_ln_kernel(
    const float* __restrict__ A, const float* __restrict__ R,
    const float* __restrict__ g, const float* __restrict__ b,
    float* __restrict__ Y, __half* __restrict__ Yh)
{
    const size_t off = (size_t)blockIdx.x * E_DIM;
    const int tid = threadIdx.x;
    float v[4];
    float s = 0.f, s2 = 0.f;
#pragma unroll
    for (int i = 0; i < 4; i++) {
        int c = tid + i * 256;
        float t = A[off + c] + R[off + c];
        v[i] = t; s += t; s2 += t * t;
    }
#pragma unroll
    for (int o = 16; o > 0; o >>= 1) {
        s  += __shfl_xor_sync(0xffffffffu, s,  o);
        s2 += __shfl_xor_sync(0xffffffffu, s2, o);
    }
    __shared__ float rs[8], rs2[8];
    __shared__ float s_mean, s_rstd;
    const int lane = tid & 31, wrp = tid >> 5;
    if (lane == 0) { rs[wrp] = s; rs2[wrp] = s2; }
    __syncthreads();
    if (tid == 0) {
        float a = 0.f, a2 = 0.f;
#pragma unroll
        for (int i = 0; i < 8; i++) { a += rs[i]; a2 += rs2[i]; }
        float mean = a * (1.0f / E_DIM);
        float var  = a2 * (1.0f / E_DIM) - mean * mean;
        s_mean = mean;
        s_rstd = rsqrtf(var + LN_EPS);
    }
    __syncthreads();
    const float mean = s_mean, rstd = s_rstd;
#pragma unroll
    for (int i = 0; i < 4; i++) {
        int c = tid + i * 256;
        float y = (v[i] - mean) * rstd * g[c] + b[c];
        if (Y) Y[off + c] = y;
        if (SPLIT) Yh[off + c] = __float2half(y);
    }
}

// ====================================================================
extern "C" void kernel_launch(void* const* d_in, const int* in_sizes, int n_in,
                              void* d_out, int out_size)
{
    (void)in_sizes; (void)n_in; (void)out_size;
    const float* x   = (const float*)d_in[0];
    const float* Wq  = (const float*)d_in[1];
    const float* bq  = (const float*)d_in[2];
    const float* Wk  = (const float*)d_in[3];
    const float* bk  = (const float*)d_in[4];
    const float* Wv  = (const float*)d_in[5];
    const float* bv  = (const float*)d_in[6];
    const float* g1  = (const float*)d_in[7];
    const float* be1 = (const float*)d_in[8];
    const float* W1  = (const float*)d_in[9];
    const float* b1  = (const float*)d_in[10];
    const float* W2  = (const float*)d_in[11];
    const float* b2  = (const float*)d_in[12];
    const float* g2  = (const float*)d_in[13];
    const float* be2 = (const float*)d_in[14];
    float* out = (float*)d_out;

    float *att, *x1, *f, *bqkv;
    cudaGetSymbolAddress((void**)&att,  g_att);
    cudaGetSymbolAddress((void**)&x1,   g_x1);
    cudaGetSymbolAddress((void**)&f,    g_f);
    cudaGetSymbolAddress((void**)&bqkv, g_bqkv);

    __half *xh, *x1h, *hh, *qkvh, *wqkv, *w1, *w2;
    cudaGetSymbolAddress((void**)&xh,   g_xh);
    cudaGetSymbolAddress((void**)&x1h,  g_x1h);
    cudaGetSymbolAddress((void**)&hh,   g_hh);
    cudaGetSymbolAddress((void**)&qkvh, g_qkvh);
    cudaGetSymbolAddress((void**)&wqkv, g_wqkv);
    cudaGetSymbolAddress((void**)&w1,   g_w1);
    cudaGetSymbolAddress((void**)&w2,   g_w2);

    cudaFuncSetAttribute(gemm_tn<0>, cudaFuncAttributeMaxDynamicSharedMemorySize, SMEM_TOTAL);
    cudaFuncSetAttribute(gemm_tn<1>, cudaFuncAttributeMaxDynamicSharedMemorySize, SMEM_TOTAL);
    cudaFuncSetAttribute(gemm_tn<2>, cudaFuncAttributeMaxDynamicSharedMemorySize, SMEM_TOTAL);

    dim3 blk(256);
    dim3 tblk(32, 8);

    // operand prep
    cvt_kernel<<<(M_TOT * E_DIM / 4 + 255) / 256, blk>>>(x, xh, M_TOT * E_DIM / 4);
    wtrans_kernel<<<dim3(E_DIM / 32, E_DIM / 32), tblk>>>(Wq, wqkv,                    E_DIM, E_DIM);
    wtrans_kernel<<<dim3(E_DIM / 32, E_DIM / 32), tblk>>>(Wk, wqkv + E_DIM * E_DIM,     E_DIM, E_DIM);
    wtrans_kernel<<<dim3(E_DIM / 32, E_DIM / 32), tblk>>>(Wv, wqkv + 2 * E_DIM * E_DIM, E_DIM, E_DIM);
    concat_bias_kernel<<<(3 * E_DIM + 255) / 256, blk>>>(bq, bk, bv, bqkv);
    wtrans_kernel<<<dim3(HID_DIM / 32, E_DIM / 32), tblk>>>(W1, w1, E_DIM, HID_DIM);
    wtrans_kernel<<<dim3(E_DIM / 32, HID_DIM / 32), tblk>>>(W2, w2, HID_DIM, E_DIM);

    // fused QKV projection -> fp16 [M, 3072]
    dim3 grid_qkv(3 * E_DIM / BN, M_TOT / BM);   // (24, 128)
    gemm_tn<2><<<grid_qkv, blk, SMEM_TOTAL>>>(xh, wqkv, bqkv, nullptr, qkvh, M_TOT, 3 * E_DIM, E_DIM);

    // per-window MMA attention
    attn_mma_kernel<<<NWIN, blk>>>(qkvh, att);

    // x1 = LN(x + att), emit fp32 + fp16
    add_ln_kernel<true><<<M_TOT, blk>>>(x, att, g1, be1, x1, x1h);

    // FFN1: h = relu(x1 @ W1 + b1), write fp16 h
    dim3 grid_f1(HID_DIM / BN, M_TOT / BM);      // (32, 128)
    gemm_tn<1><<<grid_f1, blk, SMEM_TOTAL>>>(x1h, w1, b1, nullptr, hh, M_TOT, HID_DIM, E_DIM);

    // FFN2: f = h @ W2 + b2 (fp32)
    dim3 grid_f2(E_DIM / BN, M_TOT / BM);        // (8, 128)
    gemm_tn<0><<<grid_f2, blk, SMEM_TOTAL>>>(hh, w2, b2, f, nullptr, M_TOT, E_DIM, HID_DIM);

    // out = LN(x1 + f)
    add_ln_kernel<false><<<M_TOT, blk>>>(x1, f, g2, be2, out, nullptr);
}